// round 1
// baseline (speedup 1.0000x reference)
#include <cuda_runtime.h>
#include <math.h>

#define BB 8
#define NN 1024
#define CC 768
#define HH 12
#define DD 64
#define M_ROWS (BB*NN)          // 8192
#define QKV_COLS (3*CC)         // 2304
#define SCALE_Q 0.125f          // 64^-0.5
#define LN_EPS 1e-5f

// ---------------- scratch (device globals: no allocation allowed) ----------------
__device__ float g_qkv[(size_t)M_ROWS * QKV_COLS];   // 75.5 MB
__device__ float g_q[(size_t)BB*HH*NN*DD];           // 25 MB, [B,H,N,D] (LN'd, *SCALE)
__device__ float g_k[(size_t)BB*HH*NN*DD];           // 25 MB, [B,H,N,D] (LN'd)
__device__ float g_v[(size_t)BB*HH*NN*DD];           // 25 MB, [B,H,N,D]
__device__ float g_y[(size_t)M_ROWS * CC];           // 25 MB, [B,N,C] attention out

// ---------------- GEMM: C[m,n] = sum_k A[m,k] * W[n,k]  (A row-major, W row-major [N,K]) ----
__global__ __launch_bounds__(256) void gemm_nt(const float* __restrict__ A,
                                               const float* __restrict__ Wt,
                                               float* __restrict__ Cmat,
                                               int Mdim, int Ndim, int Kdim) {
    __shared__ float As[8][128];
    __shared__ float Ws[8][128];
    const int tid = threadIdx.x;
    const int bm = blockIdx.y * 128;
    const int bn = blockIdx.x * 128;
    const int tx = tid & 15;
    const int ty = tid >> 4;

    float acc[8][8];
#pragma unroll
    for (int i = 0; i < 8; i++)
#pragma unroll
        for (int j = 0; j < 8; j++) acc[i][j] = 0.f;

    for (int k0 = 0; k0 < Kdim; k0 += 8) {
#pragma unroll
        for (int l = 0; l < 4; l++) {
            int i = tid + l * 256;          // 0..1023
            int m = i >> 3, kk = i & 7;
            As[kk][m] = A[(size_t)(bm + m) * Kdim + k0 + kk];
            Ws[kk][m] = Wt[(size_t)(bn + m) * Kdim + k0 + kk];
        }
        __syncthreads();
#pragma unroll
        for (int kk = 0; kk < 8; kk++) {
            float ra[8], rb[8];
#pragma unroll
            for (int i = 0; i < 8; i++) ra[i] = As[kk][ty + i * 16];
#pragma unroll
            for (int j = 0; j < 8; j++) rb[j] = Ws[kk][tx + j * 16];
#pragma unroll
            for (int i = 0; i < 8; i++)
#pragma unroll
                for (int j = 0; j < 8; j++)
                    acc[i][j] = fmaf(ra[i], rb[j], acc[i][j]);
        }
        __syncthreads();
    }
#pragma unroll
    for (int i = 0; i < 8; i++) {
        int m = bm + ty + i * 16;
#pragma unroll
        for (int j = 0; j < 8; j++)
            Cmat[(size_t)m * Ndim + bn + tx + j * 16] = acc[i][j];
    }
}

// ---------------- LayerNorm (q,k) + split into [B,H,N,D] ----------------
// one warp per (m, s, h) row of 64; lane holds elements lane and lane+32
__global__ __launch_bounds__(128) void ln_split_kernel() {
    int wg = blockIdx.x * 4 + (threadIdx.x >> 5);
    int lane = threadIdx.x & 31;
    const int total = M_ROWS * 3 * HH;
    if (wg >= total) return;
    int s = wg % 3;
    int h = (wg / 3) % HH;
    int m = wg / (3 * HH);
    const float* src = g_qkv + (size_t)m * QKV_COLS + s * CC + h * DD;
    float x0 = src[lane];
    float x1 = src[lane + 32];
    int b = m >> 10, n = m & 1023;
    float* dst = (s == 0 ? g_q : (s == 1 ? g_k : g_v)) +
                 (((size_t)(b * HH + h)) * NN + n) * DD;
    if (s == 2) { dst[lane] = x0; dst[lane + 32] = x1; return; }
    float sum = x0 + x1;
#pragma unroll
    for (int o = 16; o; o >>= 1) sum += __shfl_xor_sync(0xffffffffu, sum, o);
    float mean = sum * (1.f / 64.f);
    float d0 = x0 - mean, d1 = x1 - mean;
    float sq = d0 * d0 + d1 * d1;
#pragma unroll
    for (int o = 16; o; o >>= 1) sq += __shfl_xor_sync(0xffffffffu, sq, o);
    float rstd = rsqrtf(sq * (1.f / 64.f) + LN_EPS);
    float sc = (s == 0) ? (rstd * SCALE_Q) : rstd;
    dst[lane] = d0 * sc;
    dst[lane + 32] = d1 * sc;
}

// ---------------- Flash attention: block = (bh, qtile of 64 rows), 8 warps x 8 rows ----
// dyn smem layout (floats): qs[64*64] | ks[64*68] | vt[64*68] (v transposed) | ps[8*8*64]
#define SM_QS   0
#define SM_KS   4096
#define SM_VT   (4096 + 64*68)
#define SM_PS   (4096 + 2*64*68)
#define SM_FLOATS (4096 + 2*64*68 + 8*8*64)   // 16896 floats = 67584 B

__global__ __launch_bounds__(256) void attn_kernel() {
    extern __shared__ float sm[];
    float* qs = sm + SM_QS;
    float* ks = sm + SM_KS;
    float* vt = sm + SM_VT;
    float* ps = sm + SM_PS;

    const int tid  = threadIdx.x;
    const int lane = tid & 31;
    const int w    = tid >> 5;           // warp 0..7
    const int bh   = blockIdx.y;         // 0..95
    const int qt   = blockIdx.x;         // 0..15
    const size_t base = (size_t)bh * NN * DD;

    const float* qg = g_q + base + (size_t)qt * 64 * DD;
    for (int i = tid; i < 64 * 64; i += 256) qs[i] = qg[i];

    float m_i[8], l_i[8], o0[8], o1[8];
#pragma unroll
    for (int r = 0; r < 8; r++) { m_i[r] = -INFINITY; l_i[r] = 0.f; o0[r] = 0.f; o1[r] = 0.f; }

    const int c0 = lane, c1 = lane + 32;

    for (int t = 0; t < 16; t++) {
        __syncthreads();   // protects q load (t=0) and k/v reuse vs prior O-phase
        const float* kg = g_k + base + (size_t)t * 64 * DD;
        const float* vg = g_v + base + (size_t)t * 64 * DD;
        for (int i = tid; i < 64 * 64; i += 256) {
            int c = i >> 6, d = i & 63;
            ks[c * 68 + d] = kg[i];
            vt[d * 68 + c] = vg[i];
        }
        __syncthreads();

        // ---- S = q @ k^T, online softmax ----
#pragma unroll
        for (int r = 0; r < 8; r++) {
            const float* qrow = qs + (w * 8 + r) * 64;
            const float* k0p = ks + c0 * 68;
            const float* k1p = ks + c1 * 68;
            float s0 = 0.f, s1 = 0.f;
#pragma unroll
            for (int d = 0; d < 64; d += 4) {
                float4 qv = *(const float4*)(qrow + d);
                float4 ka = *(const float4*)(k0p + d);
                float4 kb = *(const float4*)(k1p + d);
                s0 += qv.x * ka.x + qv.y * ka.y + qv.z * ka.z + qv.w * ka.w;
                s1 += qv.x * kb.x + qv.y * kb.y + qv.z * kb.z + qv.w * kb.w;
            }
            float tmax = fmaxf(s0, s1);
#pragma unroll
            for (int o = 16; o; o >>= 1) tmax = fmaxf(tmax, __shfl_xor_sync(0xffffffffu, tmax, o));
            float mnew = fmaxf(m_i[r], tmax);
            float p0 = __expf(s0 - mnew);
            float p1 = __expf(s1 - mnew);
            float corr = __expf(m_i[r] - mnew);
            m_i[r] = mnew;
            float rs = p0 + p1;
#pragma unroll
            for (int o = 16; o; o >>= 1) rs += __shfl_xor_sync(0xffffffffu, rs, o);
            l_i[r] = l_i[r] * corr + rs;
            o0[r] *= corr;
            o1[r] *= corr;
            float* prow = ps + (w * 8 + r) * 64;
            prow[c0] = p0;
            prow[c1] = p1;
        }
        __syncwarp();

        // ---- O += P @ V  (lane owns d = lane, lane+32; v transposed in smem) ----
#pragma unroll
        for (int r = 0; r < 8; r++) {
            const float* prow = ps + (w * 8 + r) * 64;
            const float* v0p = vt + c0 * 68;
            const float* v1p = vt + c1 * 68;
            float a0 = o0[r], a1 = o1[r];
#pragma unroll
            for (int c = 0; c < 64; c += 4) {
                float4 pv = *(const float4*)(prow + c);
                float4 va = *(const float4*)(v0p + c);
                float4 vb = *(const float4*)(v1p + c);
                a0 += pv.x * va.x + pv.y * va.y + pv.z * va.z + pv.w * va.w;
                a1 += pv.x * vb.x + pv.y * vb.y + pv.z * vb.z + pv.w * vb.w;
            }
            o0[r] = a0;
            o1[r] = a1;
        }
    }

    // write y[b, n, h*64 + d]
    int b = bh / HH, h = bh % HH;
#pragma unroll
    for (int r = 0; r < 8; r++) {
        int n_g = qt * 64 + w * 8 + r;
        float inv = 1.f / l_i[r];
        float* yrow = g_y + ((size_t)(b * NN + n_g)) * CC + h * DD;
        yrow[c0] = o0[r] * inv;
        yrow[c1] = o1[r] * inv;
    }
}

// ---------------- launch ----------------
extern "C" void kernel_launch(void* const* d_in, const int* in_sizes, int n_in,
                              void* d_out, int out_size) {
    const float* x     = (const float*)d_in[0];
    const float* wqkv  = (const float*)d_in[1];
    const float* wproj = (const float*)d_in[2];
    float* out = (float*)d_out;

    void *p_qkv, *p_y;
    cudaGetSymbolAddress(&p_qkv, g_qkv);
    cudaGetSymbolAddress(&p_y, g_y);

    cudaFuncSetAttribute(attn_kernel, cudaFuncAttributeMaxDynamicSharedMemorySize,
                         SM_FLOATS * (int)sizeof(float));

    // 1) QKV GEMM: [8192,768] x [2304,768]^T -> [8192,2304]
    {
        dim3 grid(QKV_COLS / 128, M_ROWS / 128);
        gemm_nt<<<grid, 256>>>(x, wqkv, (float*)p_qkv, M_ROWS, QKV_COLS, CC);
    }
    // 2) LayerNorm + split
    {
        int warps = M_ROWS * 3 * HH;          // 294912
        ln_split_kernel<<<warps / 4, 128>>>();
    }
    // 3) Attention
    {
        dim3 grid(NN / 64, BB * HH);          // (16, 96)
        attn_kernel<<<grid, 256, SM_FLOATS * (int)sizeof(float)>>>();
    }
    // 4) Output projection: [8192,768] x [768,768]^T -> d_out
    {
        dim3 grid(CC / 128, M_ROWS / 128);
        gemm_nt<<<grid, 256>>>((const float*)p_y, wproj, out, M_ROWS, CC, CC);
    }
}

// round 2
// speedup vs baseline: 1.6135x; 1.6135x over previous
#include <cuda_runtime.h>
#include <math.h>
#include <stdint.h>

#define BB 8
#define NN 1024
#define CC 768
#define HH 12
#define DD 64
#define M_ROWS (BB*NN)          // 8192
#define QKV_COLS (3*CC)         // 2304
#define SCALE_Q 0.125f          // 64^-0.5
#define LN_EPS 1e-5f

// ---------------- scratch (device globals: no allocation allowed) ----------------
__device__ float g_qkv[(size_t)M_ROWS * QKV_COLS];   // 75.5 MB
__device__ float g_q[(size_t)BB*HH*NN*DD];           // [B,H,N,D] (LN'd, *SCALE)
__device__ float g_k[(size_t)BB*HH*NN*DD];           // [B,H,N,D] (LN'd)
__device__ float g_v[(size_t)BB*HH*NN*DD];           // [B,H,N,D]
__device__ float g_y[(size_t)M_ROWS * CC];           // [B,N,C] attention out

// ---------------- helpers ----------------
__device__ __forceinline__ uint32_t f2tf(float x) {
    uint32_t u;
    asm("cvt.rna.tf32.f32 %0, %1;" : "=r"(u) : "f"(x));
    return u;
}
__device__ __forceinline__ void cp16(uint32_t s, const void* g) {
    asm volatile("cp.async.cg.shared.global [%0], [%1], 16;" :: "r"(s), "l"(g));
}

// ---------------- tf32 tensor-core GEMM: C[m,n] = sum_k A[m,k]*W[n,k] ----------------
// 128x128 tile, BK=32, 256 threads (8 warps -> 2x4 warp grid, warp tile 64x32)
#define GBK  32
#define GSTR 36                         // padded floats per smem row (conflict-free frags)
#define TILE_F (128*GSTR)               // floats per stage per operand

__global__ __launch_bounds__(256, 2) void gemm_tf32(const float* __restrict__ A,
                                                    const float* __restrict__ W,
                                                    float* __restrict__ Cmat,
                                                    int Mdim, int Ndim, int Kdim) {
    extern __shared__ float sm[];
    float* As = sm;                     // [2][TILE_F]
    float* Bs = sm + 2 * TILE_F;        // [2][TILE_F]

    const int tid = threadIdx.x;
    const int bm = blockIdx.y * 128;
    const int bn = blockIdx.x * 128;
    const int lane = tid & 31;
    const int w = tid >> 5;
    const int wm = (w & 1) * 64;
    const int wn = (w >> 1) * 32;
    const int g = lane >> 2;            // groupID
    const int t = lane & 3;             // thread-in-group

    uint32_t sA0 = (uint32_t)__cvta_generic_to_shared(As);
    uint32_t sB0 = (uint32_t)__cvta_generic_to_shared(Bs);

    float c[4][4][4];
#pragma unroll
    for (int mi = 0; mi < 4; mi++)
#pragma unroll
        for (int ni = 0; ni < 4; ni++)
#pragma unroll
            for (int r = 0; r < 4; r++) c[mi][ni][r] = 0.f;

    const int KT = Kdim / GBK;

    // prologue: stage 0
    {
#pragma unroll
        for (int l = 0; l < 4; l++) {
            int i = tid + l * 256;
            int m = i >> 3, kc = (i & 7) * 4;
            cp16(sA0 + (uint32_t)(m * GSTR + kc) * 4, A + (size_t)(bm + m) * Kdim + kc);
            cp16(sB0 + (uint32_t)(m * GSTR + kc) * 4, W + (size_t)(bn + m) * Kdim + kc);
        }
        asm volatile("cp.async.commit_group;");
    }

    for (int kt = 0; kt < KT; kt++) {
        int buf = kt & 1;
        if (kt + 1 < KT) {
            int k0 = (kt + 1) * GBK;
            uint32_t dA = sA0 + (uint32_t)((buf ^ 1) * TILE_F) * 4;
            uint32_t dB = sB0 + (uint32_t)((buf ^ 1) * TILE_F) * 4;
#pragma unroll
            for (int l = 0; l < 4; l++) {
                int i = tid + l * 256;
                int m = i >> 3, kc = (i & 7) * 4;
                cp16(dA + (uint32_t)(m * GSTR + kc) * 4, A + (size_t)(bm + m) * Kdim + k0 + kc);
                cp16(dB + (uint32_t)(m * GSTR + kc) * 4, W + (size_t)(bn + m) * Kdim + k0 + kc);
            }
            asm volatile("cp.async.commit_group;");
            asm volatile("cp.async.wait_group 1;");
        } else {
            asm volatile("cp.async.wait_group 0;");
        }
        __syncthreads();

        const float* Ab = As + buf * TILE_F;
        const float* Bb = Bs + buf * TILE_F;
#pragma unroll
        for (int kk = 0; kk < 4; kk++) {
            const int k8 = kk * 8;
            uint32_t af[4][4], bf[4][2];
#pragma unroll
            for (int mi = 0; mi < 4; mi++) {
                const float* p = Ab + (wm + mi * 16 + g) * GSTR + k8 + t;
                const float* p8 = p + 8 * GSTR;
                af[mi][0] = f2tf(p[0]);
                af[mi][1] = f2tf(p8[0]);
                af[mi][2] = f2tf(p[4]);
                af[mi][3] = f2tf(p8[4]);
            }
#pragma unroll
            for (int ni = 0; ni < 4; ni++) {
                const float* p = Bb + (wn + ni * 8 + g) * GSTR + k8 + t;
                bf[ni][0] = f2tf(p[0]);
                bf[ni][1] = f2tf(p[4]);
            }
#pragma unroll
            for (int mi = 0; mi < 4; mi++)
#pragma unroll
                for (int ni = 0; ni < 4; ni++)
                    asm volatile(
                        "mma.sync.aligned.m16n8k8.row.col.f32.tf32.tf32.f32 "
                        "{%0,%1,%2,%3},{%4,%5,%6,%7},{%8,%9},{%0,%1,%2,%3};"
                        : "+f"(c[mi][ni][0]), "+f"(c[mi][ni][1]),
                          "+f"(c[mi][ni][2]), "+f"(c[mi][ni][3])
                        : "r"(af[mi][0]), "r"(af[mi][1]), "r"(af[mi][2]), "r"(af[mi][3]),
                          "r"(bf[ni][0]), "r"(bf[ni][1]));
        }
        __syncthreads();
    }

    // epilogue: c0,c1 -> (row g, cols 2t,2t+1); c2,c3 -> row g+8
#pragma unroll
    for (int mi = 0; mi < 4; mi++) {
#pragma unroll
        for (int ni = 0; ni < 4; ni++) {
            int gm = bm + wm + mi * 16 + g;
            int gn = bn + wn + ni * 8 + 2 * t;
            *(float2*)&Cmat[(size_t)gm * Ndim + gn] = make_float2(c[mi][ni][0], c[mi][ni][1]);
            *(float2*)&Cmat[(size_t)(gm + 8) * Ndim + gn] = make_float2(c[mi][ni][2], c[mi][ni][3]);
        }
    }
}

// ---------------- LayerNorm (q,k) + split into [B,H,N,D] ----------------
__global__ __launch_bounds__(128) void ln_split_kernel() {
    int wg = blockIdx.x * 4 + (threadIdx.x >> 5);
    int lane = threadIdx.x & 31;
    const int total = M_ROWS * 3 * HH;
    if (wg >= total) return;
    int s = wg % 3;
    int h = (wg / 3) % HH;
    int m = wg / (3 * HH);
    const float* src = g_qkv + (size_t)m * QKV_COLS + s * CC + h * DD;
    float x0 = src[lane];
    float x1 = src[lane + 32];
    int b = m >> 10, n = m & 1023;
    float* dst = (s == 0 ? g_q : (s == 1 ? g_k : g_v)) +
                 (((size_t)(b * HH + h)) * NN + n) * DD;
    if (s == 2) { dst[lane] = x0; dst[lane + 32] = x1; return; }
    float sum = x0 + x1;
#pragma unroll
    for (int o = 16; o; o >>= 1) sum += __shfl_xor_sync(0xffffffffu, sum, o);
    float mean = sum * (1.f / 64.f);
    float d0 = x0 - mean, d1 = x1 - mean;
    float sq = d0 * d0 + d1 * d1;
#pragma unroll
    for (int o = 16; o; o >>= 1) sq += __shfl_xor_sync(0xffffffffu, sq, o);
    float rstd = rsqrtf(sq * (1.f / 64.f) + LN_EPS);
    float sc = (s == 0) ? (rstd * SCALE_Q) : rstd;
    dst[lane] = d0 * sc;
    dst[lane + 32] = d1 * sc;
}

// ---------------- Flash attention (fp32 SIMT, unchanged this round) ----------------
#define SM_QS   0
#define SM_KS   4096
#define SM_VT   (4096 + 64*68)
#define SM_PS   (4096 + 2*64*68)
#define SM_FLOATS (4096 + 2*64*68 + 8*8*64)   // 16896 floats = 67584 B

__global__ __launch_bounds__(256) void attn_kernel() {
    extern __shared__ float sm[];
    float* qs = sm + SM_QS;
    float* ks = sm + SM_KS;
    float* vt = sm + SM_VT;
    float* ps = sm + SM_PS;

    const int tid  = threadIdx.x;
    const int lane = tid & 31;
    const int w    = tid >> 5;
    const int bh   = blockIdx.y;
    const int qt   = blockIdx.x;
    const size_t base = (size_t)bh * NN * DD;

    const float* qg = g_q + base + (size_t)qt * 64 * DD;
    for (int i = tid; i < 64 * 64; i += 256) qs[i] = qg[i];

    float m_i[8], l_i[8], o0[8], o1[8];
#pragma unroll
    for (int r = 0; r < 8; r++) { m_i[r] = -INFINITY; l_i[r] = 0.f; o0[r] = 0.f; o1[r] = 0.f; }

    const int c0 = lane, c1 = lane + 32;

    for (int t = 0; t < 16; t++) {
        __syncthreads();
        const float* kg = g_k + base + (size_t)t * 64 * DD;
        const float* vg = g_v + base + (size_t)t * 64 * DD;
        for (int i = tid; i < 64 * 64; i += 256) {
            int c = i >> 6, d = i & 63;
            ks[c * 68 + d] = kg[i];
            vt[d * 68 + c] = vg[i];
        }
        __syncthreads();

#pragma unroll
        for (int r = 0; r < 8; r++) {
            const float* qrow = qs + (w * 8 + r) * 64;
            const float* k0p = ks + c0 * 68;
            const float* k1p = ks + c1 * 68;
            float s0 = 0.f, s1 = 0.f;
#pragma unroll
            for (int d = 0; d < 64; d += 4) {
                float4 qv = *(const float4*)(qrow + d);
                float4 ka = *(const float4*)(k0p + d);
                float4 kb = *(const float4*)(k1p + d);
                s0 += qv.x * ka.x + qv.y * ka.y + qv.z * ka.z + qv.w * ka.w;
                s1 += qv.x * kb.x + qv.y * kb.y + qv.z * kb.z + qv.w * kb.w;
            }
            float tmax = fmaxf(s0, s1);
#pragma unroll
            for (int o = 16; o; o >>= 1) tmax = fmaxf(tmax, __shfl_xor_sync(0xffffffffu, tmax, o));
            float mnew = fmaxf(m_i[r], tmax);
            float p0 = __expf(s0 - mnew);
            float p1 = __expf(s1 - mnew);
            float corr = __expf(m_i[r] - mnew);
            m_i[r] = mnew;
            float rs = p0 + p1;
#pragma unroll
            for (int o = 16; o; o >>= 1) rs += __shfl_xor_sync(0xffffffffu, rs, o);
            l_i[r] = l_i[r] * corr + rs;
            o0[r] *= corr;
            o1[r] *= corr;
            float* prow = ps + (w * 8 + r) * 64;
            prow[c0] = p0;
            prow[c1] = p1;
        }
        __syncwarp();

#pragma unroll
        for (int r = 0; r < 8; r++) {
            const float* prow = ps + (w * 8 + r) * 64;
            const float* v0p = vt + c0 * 68;
            const float* v1p = vt + c1 * 68;
            float a0 = o0[r], a1 = o1[r];
#pragma unroll
            for (int c = 0; c < 64; c += 4) {
                float4 pv = *(const float4*)(prow + c);
                float4 va = *(const float4*)(v0p + c);
                float4 vb = *(const float4*)(v1p + c);
                a0 += pv.x * va.x + pv.y * va.y + pv.z * va.z + pv.w * va.w;
                a1 += pv.x * vb.x + pv.y * vb.y + pv.z * vb.z + pv.w * vb.w;
            }
            o0[r] = a0;
            o1[r] = a1;
        }
    }

    int b = bh / HH, h = bh % HH;
#pragma unroll
    for (int r = 0; r < 8; r++) {
        int n_g = qt * 64 + w * 8 + r;
        float inv = 1.f / l_i[r];
        float* yrow = g_y + ((size_t)(b * NN + n_g)) * CC + h * DD;
        yrow[c0] = o0[r] * inv;
        yrow[c1] = o1[r] * inv;
    }
}

// ---------------- launch ----------------
extern "C" void kernel_launch(void* const* d_in, const int* in_sizes, int n_in,
                              void* d_out, int out_size) {
    const float* x     = (const float*)d_in[0];
    const float* wqkv  = (const float*)d_in[1];
    const float* wproj = (const float*)d_in[2];
    float* out = (float*)d_out;

    void *p_qkv, *p_y;
    cudaGetSymbolAddress(&p_qkv, g_qkv);
    cudaGetSymbolAddress(&p_y, g_y);

    const int gemm_smem = 4 * TILE_F * (int)sizeof(float);   // 73728 B
    cudaFuncSetAttribute(gemm_tf32, cudaFuncAttributeMaxDynamicSharedMemorySize, gemm_smem);
    cudaFuncSetAttribute(attn_kernel, cudaFuncAttributeMaxDynamicSharedMemorySize,
                         SM_FLOATS * (int)sizeof(float));

    // 1) QKV GEMM: [8192,768] x [2304,768]^T -> [8192,2304]
    {
        dim3 grid(QKV_COLS / 128, M_ROWS / 128);
        gemm_tf32<<<grid, 256, gemm_smem>>>(x, wqkv, (float*)p_qkv, M_ROWS, QKV_COLS, CC);
    }
    // 2) LayerNorm + split
    {
        int warps = M_ROWS * 3 * HH;
        ln_split_kernel<<<warps / 4, 128>>>();
    }
    // 3) Attention
    {
        dim3 grid(NN / 64, BB * HH);
        attn_kernel<<<grid, 256, SM_FLOATS * (int)sizeof(float)>>>();
    }
    // 4) Output projection: [8192,768] x [768,768]^T -> d_out
    {
        dim3 grid(CC / 128, M_ROWS / 128);
        gemm_tf32<<<grid, 256, gemm_smem>>>((const float*)p_y, wproj, out, M_ROWS, CC, CC);
    }
}

// round 3
// speedup vs baseline: 4.4119x; 2.7344x over previous
#include <cuda_runtime.h>
#include <math.h>
#include <stdint.h>

#define BB 8
#define NN 1024
#define CC 768
#define HH 12
#define DD 64
#define M_ROWS (BB*NN)          // 8192
#define QKV_COLS (3*CC)         // 2304
#define SCALE_Q 0.125f          // 64^-0.5
#define LOG2E 1.4426950408889634f
#define LN_EPS 1e-5f

// ---------------- scratch ----------------
__device__ float g_qkv[(size_t)M_ROWS * QKV_COLS];
__device__ float g_q[(size_t)BB*HH*NN*DD];   // LN'd, * (SCALE_Q*LOG2E)
__device__ float g_k[(size_t)BB*HH*NN*DD];   // LN'd
__device__ float g_v[(size_t)BB*HH*NN*DD];
__device__ float g_y[(size_t)M_ROWS * CC];

// ---------------- helpers ----------------
__device__ __forceinline__ uint32_t f2tf(float x) {
    uint32_t u;
    asm("cvt.rna.tf32.f32 %0, %1;" : "=r"(u) : "f"(x));
    return u;
}
__device__ __forceinline__ void cp16(uint32_t s, const void* g) {
    asm volatile("cp.async.cg.shared.global [%0], [%1], 16;" :: "r"(s), "l"(g));
}
#define MMA_TF32(C, A0, A1, A2, A3, B0, B1)                                   \
    asm volatile(                                                             \
        "mma.sync.aligned.m16n8k8.row.col.f32.tf32.tf32.f32 "                 \
        "{%0,%1,%2,%3},{%4,%5,%6,%7},{%8,%9},{%0,%1,%2,%3};"                  \
        : "+f"(C[0]), "+f"(C[1]), "+f"(C[2]), "+f"(C[3])                      \
        : "r"(A0), "r"(A1), "r"(A2), "r"(A3), "r"(B0), "r"(B1))

// ---------------- tf32 tensor-core GEMM (unchanged from R2) ----------------
#define GBK  32
#define GSTR 36
#define TILE_F (128*GSTR)

__global__ __launch_bounds__(256, 2) void gemm_tf32(const float* __restrict__ A,
                                                    const float* __restrict__ W,
                                                    float* __restrict__ Cmat,
                                                    int Mdim, int Ndim, int Kdim) {
    extern __shared__ float sm[];
    float* As = sm;
    float* Bs = sm + 2 * TILE_F;

    const int tid = threadIdx.x;
    const int bm = blockIdx.y * 128;
    const int bn = blockIdx.x * 128;
    const int lane = tid & 31;
    const int w = tid >> 5;
    const int wm = (w & 1) * 64;
    const int wn = (w >> 1) * 32;
    const int g = lane >> 2;
    const int t = lane & 3;

    uint32_t sA0 = (uint32_t)__cvta_generic_to_shared(As);
    uint32_t sB0 = (uint32_t)__cvta_generic_to_shared(Bs);

    float c[4][4][4];
#pragma unroll
    for (int mi = 0; mi < 4; mi++)
#pragma unroll
        for (int ni = 0; ni < 4; ni++)
#pragma unroll
            for (int r = 0; r < 4; r++) c[mi][ni][r] = 0.f;

    const int KT = Kdim / GBK;
    {
#pragma unroll
        for (int l = 0; l < 4; l++) {
            int i = tid + l * 256;
            int m = i >> 3, kc = (i & 7) * 4;
            cp16(sA0 + (uint32_t)(m * GSTR + kc) * 4, A + (size_t)(bm + m) * Kdim + kc);
            cp16(sB0 + (uint32_t)(m * GSTR + kc) * 4, W + (size_t)(bn + m) * Kdim + kc);
        }
        asm volatile("cp.async.commit_group;");
    }

    for (int kt = 0; kt < KT; kt++) {
        int buf = kt & 1;
        if (kt + 1 < KT) {
            int k0 = (kt + 1) * GBK;
            uint32_t dA = sA0 + (uint32_t)((buf ^ 1) * TILE_F) * 4;
            uint32_t dB = sB0 + (uint32_t)((buf ^ 1) * TILE_F) * 4;
#pragma unroll
            for (int l = 0; l < 4; l++) {
                int i = tid + l * 256;
                int m = i >> 3, kc = (i & 7) * 4;
                cp16(dA + (uint32_t)(m * GSTR + kc) * 4, A + (size_t)(bm + m) * Kdim + k0 + kc);
                cp16(dB + (uint32_t)(m * GSTR + kc) * 4, W + (size_t)(bn + m) * Kdim + k0 + kc);
            }
            asm volatile("cp.async.commit_group;");
            asm volatile("cp.async.wait_group 1;");
        } else {
            asm volatile("cp.async.wait_group 0;");
        }
        __syncthreads();

        const float* Ab = As + buf * TILE_F;
        const float* Bb = Bs + buf * TILE_F;
#pragma unroll
        for (int kk = 0; kk < 4; kk++) {
            const int k8 = kk * 8;
            uint32_t af[4][4], bf[4][2];
#pragma unroll
            for (int mi = 0; mi < 4; mi++) {
                const float* p = Ab + (wm + mi * 16 + g) * GSTR + k8 + t;
                const float* p8 = p + 8 * GSTR;
                af[mi][0] = f2tf(p[0]);
                af[mi][1] = f2tf(p8[0]);
                af[mi][2] = f2tf(p[4]);
                af[mi][3] = f2tf(p8[4]);
            }
#pragma unroll
            for (int ni = 0; ni < 4; ni++) {
                const float* p = Bb + (wn + ni * 8 + g) * GSTR + k8 + t;
                bf[ni][0] = f2tf(p[0]);
                bf[ni][1] = f2tf(p[4]);
            }
#pragma unroll
            for (int mi = 0; mi < 4; mi++)
#pragma unroll
                for (int ni = 0; ni < 4; ni++)
                    MMA_TF32(c[mi][ni], af[mi][0], af[mi][1], af[mi][2], af[mi][3],
                             bf[ni][0], bf[ni][1]);
        }
        __syncthreads();
    }

#pragma unroll
    for (int mi = 0; mi < 4; mi++) {
#pragma unroll
        for (int ni = 0; ni < 4; ni++) {
            int gm = bm + wm + mi * 16 + g;
            int gn = bn + wn + ni * 8 + 2 * t;
            *(float2*)&Cmat[(size_t)gm * Ndim + gn] = make_float2(c[mi][ni][0], c[mi][ni][1]);
            *(float2*)&Cmat[(size_t)(gm + 8) * Ndim + gn] = make_float2(c[mi][ni][2], c[mi][ni][3]);
        }
    }
}

// ---------------- LayerNorm (q,k) + split; q gets SCALE_Q*LOG2E ----------------
__global__ __launch_bounds__(128) void ln_split_kernel() {
    int wg = blockIdx.x * 4 + (threadIdx.x >> 5);
    int lane = threadIdx.x & 31;
    const int total = M_ROWS * 3 * HH;
    if (wg >= total) return;
    int s = wg % 3;
    int h = (wg / 3) % HH;
    int m = wg / (3 * HH);
    const float* src = g_qkv + (size_t)m * QKV_COLS + s * CC + h * DD;
    float x0 = src[lane];
    float x1 = src[lane + 32];
    int b = m >> 10, n = m & 1023;
    float* dst = (s == 0 ? g_q : (s == 1 ? g_k : g_v)) +
                 (((size_t)(b * HH + h)) * NN + n) * DD;
    if (s == 2) { dst[lane] = x0; dst[lane + 32] = x1; return; }
    float sum = x0 + x1;
#pragma unroll
    for (int o = 16; o; o >>= 1) sum += __shfl_xor_sync(0xffffffffu, sum, o);
    float mean = sum * (1.f / 64.f);
    float d0 = x0 - mean, d1 = x1 - mean;
    float sq = d0 * d0 + d1 * d1;
#pragma unroll
    for (int o = 16; o; o >>= 1) sq += __shfl_xor_sync(0xffffffffu, sq, o);
    float rstd = rsqrtf(sq * (1.f / 64.f) + LN_EPS);
    float sc = (s == 0) ? (rstd * SCALE_Q * LOG2E) : rstd;
    dst[lane] = d0 * sc;
    dst[lane + 32] = d1 * sc;
}

// ---------------- tensor-core flash attention ----------------
// block: 128 q rows x one bh. 8 warps, each warp 16 q rows.
// smem (uint32/tf32): qs[128*68] | ks[64*68] | vs[64*68] | ps[128*68]
#define AST 68
#define AQ_OFF 0
#define AK_OFF (128*AST)
#define AV_OFF (128*AST + 64*AST)
#define AP_OFF (128*AST + 2*64*AST)
#define A_SMEM_U32 (2*128*AST + 2*64*AST)   // 26112 u32 = 104448 B

__global__ __launch_bounds__(256, 2) void attn_mma() {
    extern __shared__ uint32_t smu[];
    uint32_t* qsu = smu + AQ_OFF;
    uint32_t* ksu = smu + AK_OFF;
    uint32_t* vsu = smu + AV_OFF;
    uint32_t* psu = smu + AP_OFF;

    const int tid = threadIdx.x;
    const int lane = tid & 31;
    const int w = tid >> 5;
    const int g = lane >> 2;
    const int t = lane & 3;
    const int mrow = w * 16;
    const int bh = blockIdx.y;
    const int qt = blockIdx.x;
    const size_t base = (size_t)bh * NN * DD;

    // stage Q tile (128x64) as tf32
    {
        const float4* qg4 = (const float4*)(g_q + base + (size_t)qt * 128 * DD);
#pragma unroll
        for (int l = 0; l < 8; l++) {
            int i = tid + l * 256;           // 0..2047 float4s
            int row = i >> 4, c4 = (i & 15) << 2;
            float4 v = qg4[i];
            uint4 u = make_uint4(f2tf(v.x), f2tf(v.y), f2tf(v.z), f2tf(v.w));
            *(uint4*)&qsu[row * AST + c4] = u;
        }
    }

    float m0 = -INFINITY, m1 = -INFINITY, l0 = 0.f, l1 = 0.f;
    float o[8][4];
#pragma unroll
    for (int ni = 0; ni < 8; ni++)
#pragma unroll
        for (int r = 0; r < 4; r++) o[ni][r] = 0.f;

    const int r0 = mrow + g, r1 = mrow + g + 8;

    for (int tkv = 0; tkv < 16; tkv++) {
        __syncthreads();
        // load K,V tiles (64x64 each) as tf32
        {
            const float4* kg4 = (const float4*)(g_k + base + (size_t)tkv * 64 * DD);
            const float4* vg4 = (const float4*)(g_v + base + (size_t)tkv * 64 * DD);
#pragma unroll
            for (int l = 0; l < 4; l++) {
                int i = tid + l * 256;       // 0..1023
                int row = i >> 4, c4 = (i & 15) << 2;
                float4 kv = kg4[i];
                float4 vv = vg4[i];
                *(uint4*)&ksu[row * AST + c4] =
                    make_uint4(f2tf(kv.x), f2tf(kv.y), f2tf(kv.z), f2tf(kv.w));
                *(uint4*)&vsu[row * AST + c4] =
                    make_uint4(f2tf(vv.x), f2tf(vv.y), f2tf(vv.z), f2tf(vv.w));
            }
        }
        __syncthreads();

        // ---- S = Q @ K^T ----
        float s[8][4];
#pragma unroll
        for (int ni = 0; ni < 8; ni++)
#pragma unroll
            for (int r = 0; r < 4; r++) s[ni][r] = 0.f;

#pragma unroll
        for (int kk = 0; kk < 8; kk++) {
            const int k8 = kk * 8;
            uint32_t a0 = qsu[r0 * AST + k8 + t];
            uint32_t a1 = qsu[r1 * AST + k8 + t];
            uint32_t a2 = qsu[r0 * AST + k8 + t + 4];
            uint32_t a3 = qsu[r1 * AST + k8 + t + 4];
#pragma unroll
            for (int ni = 0; ni < 8; ni++) {
                uint32_t b0 = ksu[(ni * 8 + g) * AST + k8 + t];
                uint32_t b1 = ksu[(ni * 8 + g) * AST + k8 + t + 4];
                MMA_TF32(s[ni], a0, a1, a2, a3, b0, b1);
            }
        }

        // ---- online softmax (log2 domain; scores already * log2(e)) ----
        float mx0 = s[0][0], mx1 = s[0][2];
#pragma unroll
        for (int ni = 0; ni < 8; ni++) {
            mx0 = fmaxf(mx0, fmaxf(s[ni][0], s[ni][1]));
            mx1 = fmaxf(mx1, fmaxf(s[ni][2], s[ni][3]));
        }
        mx0 = fmaxf(mx0, __shfl_xor_sync(0xffffffffu, mx0, 1));
        mx0 = fmaxf(mx0, __shfl_xor_sync(0xffffffffu, mx0, 2));
        mx1 = fmaxf(mx1, __shfl_xor_sync(0xffffffffu, mx1, 1));
        mx1 = fmaxf(mx1, __shfl_xor_sync(0xffffffffu, mx1, 2));
        float mn0 = fmaxf(m0, mx0), mn1 = fmaxf(m1, mx1);
        float corr0 = exp2f(m0 - mn0), corr1 = exp2f(m1 - mn1);
        m0 = mn0; m1 = mn1;

        float rs0 = 0.f, rs1 = 0.f;
#pragma unroll
        for (int ni = 0; ni < 8; ni++) {
            s[ni][0] = exp2f(s[ni][0] - mn0);
            s[ni][1] = exp2f(s[ni][1] - mn0);
            s[ni][2] = exp2f(s[ni][2] - mn1);
            s[ni][3] = exp2f(s[ni][3] - mn1);
            rs0 += s[ni][0] + s[ni][1];
            rs1 += s[ni][2] + s[ni][3];
        }
        rs0 += __shfl_xor_sync(0xffffffffu, rs0, 1);
        rs0 += __shfl_xor_sync(0xffffffffu, rs0, 2);
        rs1 += __shfl_xor_sync(0xffffffffu, rs1, 1);
        rs1 += __shfl_xor_sync(0xffffffffu, rs1, 2);
        l0 = l0 * corr0 + rs0;
        l1 = l1 * corr1 + rs1;

#pragma unroll
        for (int ni = 0; ni < 8; ni++) {
            o[ni][0] *= corr0; o[ni][1] *= corr0;
            o[ni][2] *= corr1; o[ni][3] *= corr1;
        }

        // ---- store P (tf32) to per-warp smem rows, relayout to A-frags ----
#pragma unroll
        for (int ni = 0; ni < 8; ni++) {
            *(uint2*)&psu[r0 * AST + ni * 8 + 2 * t] =
                make_uint2(f2tf(s[ni][0]), f2tf(s[ni][1]));
            *(uint2*)&psu[r1 * AST + ni * 8 + 2 * t] =
                make_uint2(f2tf(s[ni][2]), f2tf(s[ni][3]));
        }
        __syncwarp();

        // ---- O += P @ V ----
#pragma unroll
        for (int kk = 0; kk < 8; kk++) {
            const int k8 = kk * 8;
            uint32_t a0 = psu[r0 * AST + k8 + t];
            uint32_t a1 = psu[r1 * AST + k8 + t];
            uint32_t a2 = psu[r0 * AST + k8 + t + 4];
            uint32_t a3 = psu[r1 * AST + k8 + t + 4];
#pragma unroll
            for (int ni = 0; ni < 8; ni++) {
                uint32_t b0 = vsu[(k8 + t) * AST + ni * 8 + g];
                uint32_t b1 = vsu[(k8 + t + 4) * AST + ni * 8 + g];
                MMA_TF32(o[ni], a0, a1, a2, a3, b0, b1);
            }
        }
    }

    // ---- write out: y[b, n, h*64 + d] ----
    int b = bh / HH, h = bh % HH;
    float inv0 = 1.f / l0, inv1 = 1.f / l1;
    int n0 = qt * 128 + r0, n1 = qt * 128 + r1;
    float* y0 = g_y + ((size_t)(b * NN + n0)) * CC + h * DD;
    float* y1 = g_y + ((size_t)(b * NN + n1)) * CC + h * DD;
#pragma unroll
    for (int ni = 0; ni < 8; ni++) {
        *(float2*)&y0[ni * 8 + 2 * t] = make_float2(o[ni][0] * inv0, o[ni][1] * inv0);
        *(float2*)&y1[ni * 8 + 2 * t] = make_float2(o[ni][2] * inv1, o[ni][3] * inv1);
    }
}

// ---------------- launch ----------------
extern "C" void kernel_launch(void* const* d_in, const int* in_sizes, int n_in,
                              void* d_out, int out_size) {
    const float* x     = (const float*)d_in[0];
    const float* wqkv  = (const float*)d_in[1];
    const float* wproj = (const float*)d_in[2];
    float* out = (float*)d_out;

    void *p_qkv, *p_y;
    cudaGetSymbolAddress(&p_qkv, g_qkv);
    cudaGetSymbolAddress(&p_y, g_y);

    const int gemm_smem = 4 * TILE_F * (int)sizeof(float);
    cudaFuncSetAttribute(gemm_tf32, cudaFuncAttributeMaxDynamicSharedMemorySize, gemm_smem);
    const int attn_smem = A_SMEM_U32 * (int)sizeof(uint32_t);   // 104448
    cudaFuncSetAttribute(attn_mma, cudaFuncAttributeMaxDynamicSharedMemorySize, attn_smem);

    // 1) QKV GEMM
    {
        dim3 grid(QKV_COLS / 128, M_ROWS / 128);
        gemm_tf32<<<grid, 256, gemm_smem>>>(x, wqkv, (float*)p_qkv, M_ROWS, QKV_COLS, CC);
    }
    // 2) LayerNorm + split
    {
        int warps = M_ROWS * 3 * HH;
        ln_split_kernel<<<warps / 4, 128>>>();
    }
    // 3) Attention (tensor core)
    {
        dim3 grid(NN / 128, BB * HH);
        attn_mma<<<grid, 256, attn_smem>>>();
    }
    // 4) Output projection
    {
        dim3 grid(CC / 128, M_ROWS / 128);
        gemm_tf32<<<grid, 256, gemm_smem>>>((const float*)p_y, wproj, out, M_ROWS, CC, CC);
    }
}

// round 4
// speedup vs baseline: 4.9158x; 1.1142x over previous
#include <cuda_runtime.h>
#include <math.h>
#include <stdint.h>

#define BB 8
#define NN 1024
#define CC 768
#define HH 12
#define DD 64
#define M_ROWS (BB*NN)          // 8192
#define QKV_COLS (3*CC)         // 2304
#define SCALE_Q 0.125f
#define LOG2E 1.4426950408889634f
#define LN_EPS 1e-5f

// ---------------- scratch (tf32 payloads stored as uint32) ----------------
__device__ uint32_t g_xt[(size_t)M_ROWS * CC];        // x as tf32
__device__ uint32_t g_wqkvt[(size_t)QKV_COLS * CC];   // wqkv as tf32
__device__ uint32_t g_wprojt[(size_t)CC * CC];        // wproj as tf32
__device__ uint32_t g_q[(size_t)BB*HH*NN*DD];         // LN'd * (SCALE_Q*LOG2E), tf32
__device__ uint32_t g_k[(size_t)BB*HH*NN*DD];         // LN'd, tf32
__device__ uint32_t g_v[(size_t)BB*HH*NN*DD];         // tf32
__device__ uint32_t g_y[(size_t)M_ROWS * CC];         // attn out, tf32

// ---------------- helpers ----------------
__device__ __forceinline__ uint32_t f2tf(float x) {
    uint32_t u;
    asm("cvt.rna.tf32.f32 %0, %1;" : "=r"(u) : "f"(x));
    return u;
}
__device__ __forceinline__ void cp16(uint32_t s, const void* g) {
    asm volatile("cp.async.cg.shared.global [%0], [%1], 16;" :: "r"(s), "l"(g));
}
#define MMA_TF32(C, A0, A1, A2, A3, B0, B1)                                   \
    asm volatile(                                                             \
        "mma.sync.aligned.m16n8k8.row.col.f32.tf32.tf32.f32 "                 \
        "{%0,%1,%2,%3},{%4,%5,%6,%7},{%8,%9},{%0,%1,%2,%3};"                  \
        : "+f"(C[0]), "+f"(C[1]), "+f"(C[2]), "+f"(C[3])                      \
        : "r"(A0), "r"(A1), "r"(A2), "r"(A3), "r"(B0), "r"(B1))

// ---------------- fp32 -> tf32 bulk convert ----------------
__global__ __launch_bounds__(256) void conv_tf32(const float4* __restrict__ in,
                                                 uint4* __restrict__ out, int n4) {
    int i = blockIdx.x * 256 + threadIdx.x;
    if (i < n4) {
        float4 v = in[i];
        out[i] = make_uint4(f2tf(v.x), f2tf(v.y), f2tf(v.z), f2tf(v.w));
    }
}

// ---------------- GEMM core (tf32-uint operands) ----------------
#define GBK  32
#define GSTR 36
#define TILE_F (128*GSTR)

// mainloop macro body shared by both gemm kernels via a device function
struct Frag { float c[4][4][4]; };

__device__ __forceinline__ void gemm_mainloop(const uint32_t* __restrict__ A,
                                              const uint32_t* __restrict__ W,
                                              uint32_t* As, uint32_t* Bs,
                                              int bm, int bn, int Kdim,
                                              int tid, int wm, int wn, int g, int t,
                                              float c[4][4][4]) {
    uint32_t sA0 = (uint32_t)__cvta_generic_to_shared(As);
    uint32_t sB0 = (uint32_t)__cvta_generic_to_shared(Bs);
    const int KT = Kdim / GBK;
    {
#pragma unroll
        for (int l = 0; l < 4; l++) {
            int i = tid + l * 256;
            int m = i >> 3, kc = (i & 7) * 4;
            cp16(sA0 + (uint32_t)(m * GSTR + kc) * 4, A + (size_t)(bm + m) * Kdim + kc);
            cp16(sB0 + (uint32_t)(m * GSTR + kc) * 4, W + (size_t)(bn + m) * Kdim + kc);
        }
        asm volatile("cp.async.commit_group;");
    }
    for (int kt = 0; kt < KT; kt++) {
        int buf = kt & 1;
        if (kt + 1 < KT) {
            int k0 = (kt + 1) * GBK;
            uint32_t dA = sA0 + (uint32_t)((buf ^ 1) * TILE_F) * 4;
            uint32_t dB = sB0 + (uint32_t)((buf ^ 1) * TILE_F) * 4;
#pragma unroll
            for (int l = 0; l < 4; l++) {
                int i = tid + l * 256;
                int m = i >> 3, kc = (i & 7) * 4;
                cp16(dA + (uint32_t)(m * GSTR + kc) * 4, A + (size_t)(bm + m) * Kdim + k0 + kc);
                cp16(dB + (uint32_t)(m * GSTR + kc) * 4, W + (size_t)(bn + m) * Kdim + k0 + kc);
            }
            asm volatile("cp.async.commit_group;");
            asm volatile("cp.async.wait_group 1;");
        } else {
            asm volatile("cp.async.wait_group 0;");
        }
        __syncthreads();

        const uint32_t* Ab = As + buf * TILE_F;
        const uint32_t* Bb = Bs + buf * TILE_F;
#pragma unroll
        for (int kk = 0; kk < 4; kk++) {
            const int k8 = kk * 8;
            uint32_t af[4][4], bf[4][2];
#pragma unroll
            for (int mi = 0; mi < 4; mi++) {
                const uint32_t* p = Ab + (wm + mi * 16 + g) * GSTR + k8 + t;
                const uint32_t* p8 = p + 8 * GSTR;
                af[mi][0] = p[0];
                af[mi][1] = p8[0];
                af[mi][2] = p[4];
                af[mi][3] = p8[4];
            }
#pragma unroll
            for (int ni = 0; ni < 4; ni++) {
                const uint32_t* p = Bb + (wn + ni * 8 + g) * GSTR + k8 + t;
                bf[ni][0] = p[0];
                bf[ni][1] = p[4];
            }
#pragma unroll
            for (int mi = 0; mi < 4; mi++)
#pragma unroll
                for (int ni = 0; ni < 4; ni++)
                    MMA_TF32(c[mi][ni], af[mi][0], af[mi][1], af[mi][2], af[mi][3],
                             bf[ni][0], bf[ni][1]);
        }
        __syncthreads();
    }
}

// ---------------- proj GEMM: fp32 output ----------------
__global__ __launch_bounds__(256, 2) void gemm_proj(const uint32_t* __restrict__ A,
                                                    const uint32_t* __restrict__ W,
                                                    float* __restrict__ Cmat,
                                                    int Mdim, int Ndim, int Kdim) {
    extern __shared__ uint32_t smu[];
    uint32_t* As = smu;
    uint32_t* Bs = smu + 2 * TILE_F;
    const int tid = threadIdx.x;
    const int bm = blockIdx.y * 128;
    const int bn = blockIdx.x * 128;
    const int lane = tid & 31;
    const int w = tid >> 5;
    const int wm = (w & 1) * 64;
    const int wn = (w >> 1) * 32;
    const int g = lane >> 2;
    const int t = lane & 3;

    float c[4][4][4];
#pragma unroll
    for (int mi = 0; mi < 4; mi++)
#pragma unroll
        for (int ni = 0; ni < 4; ni++)
#pragma unroll
            for (int r = 0; r < 4; r++) c[mi][ni][r] = 0.f;

    gemm_mainloop(A, W, As, Bs, bm, bn, Kdim, tid, wm, wn, g, t, c);

#pragma unroll
    for (int mi = 0; mi < 4; mi++) {
#pragma unroll
        for (int ni = 0; ni < 4; ni++) {
            int gm = bm + wm + mi * 16 + g;
            int gn = bn + wn + ni * 8 + 2 * t;
            *(float2*)&Cmat[(size_t)gm * Ndim + gn] = make_float2(c[mi][ni][0], c[mi][ni][1]);
            *(float2*)&Cmat[(size_t)(gm + 8) * Ndim + gn] = make_float2(c[mi][ni][2], c[mi][ni][3]);
        }
    }
}

// ---------------- QKV GEMM with fused LayerNorm+split epilogue ----------------
// tile (128 rows, 128 cols) = 2 full heads of one of q/k/v. Writes g_q/g_k/g_v tf32.
__global__ __launch_bounds__(256, 2) void gemm_qkv_ln() {
    extern __shared__ uint32_t smu[];
    uint32_t* As = smu;
    uint32_t* Bs = smu + 2 * TILE_F;
    float2* psm = (float2*)(smu + 4 * TILE_F);   // [128 rows][2 head_local][2 half]

    const int tid = threadIdx.x;
    const int bm = blockIdx.y * 128;
    const int bn = blockIdx.x * 128;
    const int lane = tid & 31;
    const int w = tid >> 5;
    const int wm = (w & 1) * 64;
    const int wn = (w >> 1) * 32;
    const int g = lane >> 2;
    const int t = lane & 3;

    float c[4][4][4];
#pragma unroll
    for (int mi = 0; mi < 4; mi++)
#pragma unroll
        for (int ni = 0; ni < 4; ni++)
#pragma unroll
            for (int r = 0; r < 4; r++) c[mi][ni][r] = 0.f;

    gemm_mainloop(g_xt, g_wqkvt, As, Bs, bm, bn, CC, tid, wm, wn, g, t, c);

    const int s = bn / CC;                  // 0:q 1:k 2:v
    const int colb = bn % CC;
    const int h = (colb + wn) >> 6;         // global head for this warp's cols
    const int dbase = wn & 63;              // 0 or 32
    uint32_t* dst_arr = (s == 0) ? g_q : (s == 1 ? g_k : g_v);

    if (s == 2) {
        // plain store of v as tf32
#pragma unroll
        for (int mi = 0; mi < 4; mi++) {
#pragma unroll
            for (int r = 0; r < 2; r++) {
                int m = bm + wm + mi * 16 + g + 8 * r;
                int b = m >> 10, n = m & 1023;
                uint32_t* dst = dst_arr + (((size_t)(b * HH + h)) * NN + n) * DD + dbase;
#pragma unroll
                for (int ni = 0; ni < 4; ni++)
                    *(uint2*)&dst[ni * 8 + 2 * t] =
                        make_uint2(f2tf(c[mi][ni][2 * r]), f2tf(c[mi][ni][2 * r + 1]));
            }
        }
        return;
    }

    // --- LayerNorm epilogue for q/k ---
    const int hl = wn >> 6;                 // head_local 0/1
    const int half = (wn >> 5) & 1;         // which 32-col half of the head
    // per-lane partials over this warp's 32 cols, per owned row
#pragma unroll
    for (int mi = 0; mi < 4; mi++) {
#pragma unroll
        for (int r = 0; r < 2; r++) {
            float sum = 0.f, sq = 0.f;
#pragma unroll
            for (int ni = 0; ni < 4; ni++) {
                float v0 = c[mi][ni][2 * r], v1 = c[mi][ni][2 * r + 1];
                sum += v0 + v1;
                sq += v0 * v0 + v1 * v1;
            }
            sum += __shfl_xor_sync(0xffffffffu, sum, 1);
            sq  += __shfl_xor_sync(0xffffffffu, sq, 1);
            sum += __shfl_xor_sync(0xffffffffu, sum, 2);
            sq  += __shfl_xor_sync(0xffffffffu, sq, 2);
            if (t == 0) {
                int row = wm + mi * 16 + g + 8 * r;
                psm[row * 4 + hl * 2 + half] = make_float2(sum, sq);
            }
        }
    }
    __syncthreads();

    const float fscale = (s == 0) ? (SCALE_Q * LOG2E) : 1.0f;
#pragma unroll
    for (int mi = 0; mi < 4; mi++) {
#pragma unroll
        for (int r = 0; r < 2; r++) {
            int row = wm + mi * 16 + g + 8 * r;
            float2 pa = psm[row * 4 + hl * 2 + 0];
            float2 pb = psm[row * 4 + hl * 2 + 1];
            float mean = (pa.x + pb.x) * (1.f / 64.f);
            float var = (pa.y + pb.y) * (1.f / 64.f) - mean * mean;
            float sc = rsqrtf(var + LN_EPS) * fscale;
            int m = bm + row;
            int b = m >> 10, n = m & 1023;
            uint32_t* dst = dst_arr + (((size_t)(b * HH + h)) * NN + n) * DD + dbase;
#pragma unroll
            for (int ni = 0; ni < 4; ni++)
                *(uint2*)&dst[ni * 8 + 2 * t] =
                    make_uint2(f2tf((c[mi][ni][2 * r] - mean) * sc),
                               f2tf((c[mi][ni][2 * r + 1] - mean) * sc));
        }
    }
}

// ---------------- tensor-core flash attention (tf32 in/out) ----------------
#define AST 68
#define AQ_OFF 0
#define AK_OFF (128*AST)
#define AV_OFF (128*AST + 64*AST)
#define AP_OFF (128*AST + 2*64*AST)
#define A_SMEM_U32 (2*128*AST + 2*64*AST)   // 104448 B

__global__ __launch_bounds__(256, 2) void attn_mma() {
    extern __shared__ uint32_t smu[];
    uint32_t* qsu = smu + AQ_OFF;
    uint32_t* ksu = smu + AK_OFF;
    uint32_t* vsu = smu + AV_OFF;
    uint32_t* psu = smu + AP_OFF;

    const int tid = threadIdx.x;
    const int lane = tid & 31;
    const int w = tid >> 5;
    const int g = lane >> 2;
    const int t = lane & 3;
    const int mrow = w * 16;
    const int bh = blockIdx.y;
    const int qt = blockIdx.x;
    const size_t base = (size_t)bh * NN * DD;

    uint32_t sq0 = (uint32_t)__cvta_generic_to_shared(qsu);
    uint32_t sk0 = (uint32_t)__cvta_generic_to_shared(ksu);
    uint32_t sv0 = (uint32_t)__cvta_generic_to_shared(vsu);

    // stage Q tile (128x64, already tf32) via cp.async (committed with first KV group)
    {
        const uint32_t* qg = g_q + base + (size_t)qt * 128 * DD;
#pragma unroll
        for (int l = 0; l < 8; l++) {
            int i = tid + l * 256;
            int row = i >> 4, c4 = (i & 15) << 2;
            cp16(sq0 + (uint32_t)(row * AST + c4) * 4, qg + row * DD + c4);
        }
    }

    float m0 = -INFINITY, m1 = -INFINITY, l0 = 0.f, l1 = 0.f;
    float o[8][4];
#pragma unroll
    for (int ni = 0; ni < 8; ni++)
#pragma unroll
        for (int r = 0; r < 4; r++) o[ni][r] = 0.f;

    const int r0 = mrow + g, r1 = mrow + g + 8;

    for (int tkv = 0; tkv < 16; tkv++) {
        __syncthreads();
        {
            const uint32_t* kg = g_k + base + (size_t)tkv * 64 * DD;
            const uint32_t* vg = g_v + base + (size_t)tkv * 64 * DD;
#pragma unroll
            for (int l = 0; l < 4; l++) {
                int i = tid + l * 256;
                int row = i >> 4, c4 = (i & 15) << 2;
                cp16(sk0 + (uint32_t)(row * AST + c4) * 4, kg + row * DD + c4);
                cp16(sv0 + (uint32_t)(row * AST + c4) * 4, vg + row * DD + c4);
            }
            asm volatile("cp.async.commit_group;");
            asm volatile("cp.async.wait_group 0;");
        }
        __syncthreads();

        // ---- S = Q @ K^T ----
        float s[8][4];
#pragma unroll
        for (int ni = 0; ni < 8; ni++)
#pragma unroll
            for (int r = 0; r < 4; r++) s[ni][r] = 0.f;

#pragma unroll
        for (int kk = 0; kk < 8; kk++) {
            const int k8 = kk * 8;
            uint32_t a0 = qsu[r0 * AST + k8 + t];
            uint32_t a1 = qsu[r1 * AST + k8 + t];
            uint32_t a2 = qsu[r0 * AST + k8 + t + 4];
            uint32_t a3 = qsu[r1 * AST + k8 + t + 4];
#pragma unroll
            for (int ni = 0; ni < 8; ni++) {
                uint32_t b0 = ksu[(ni * 8 + g) * AST + k8 + t];
                uint32_t b1 = ksu[(ni * 8 + g) * AST + k8 + t + 4];
                MMA_TF32(s[ni], a0, a1, a2, a3, b0, b1);
            }
        }

        // ---- online softmax (log2 domain) ----
        float mx0 = s[0][0], mx1 = s[0][2];
#pragma unroll
        for (int ni = 0; ni < 8; ni++) {
            mx0 = fmaxf(mx0, fmaxf(s[ni][0], s[ni][1]));
            mx1 = fmaxf(mx1, fmaxf(s[ni][2], s[ni][3]));
        }
        mx0 = fmaxf(mx0, __shfl_xor_sync(0xffffffffu, mx0, 1));
        mx0 = fmaxf(mx0, __shfl_xor_sync(0xffffffffu, mx0, 2));
        mx1 = fmaxf(mx1, __shfl_xor_sync(0xffffffffu, mx1, 1));
        mx1 = fmaxf(mx1, __shfl_xor_sync(0xffffffffu, mx1, 2));
        float mn0 = fmaxf(m0, mx0), mn1 = fmaxf(m1, mx1);
        float corr0 = exp2f(m0 - mn0), corr1 = exp2f(m1 - mn1);
        m0 = mn0; m1 = mn1;

        float rs0 = 0.f, rs1 = 0.f;
#pragma unroll
        for (int ni = 0; ni < 8; ni++) {
            s[ni][0] = exp2f(s[ni][0] - mn0);
            s[ni][1] = exp2f(s[ni][1] - mn0);
            s[ni][2] = exp2f(s[ni][2] - mn1);
            s[ni][3] = exp2f(s[ni][3] - mn1);
            rs0 += s[ni][0] + s[ni][1];
            rs1 += s[ni][2] + s[ni][3];
        }
        rs0 += __shfl_xor_sync(0xffffffffu, rs0, 1);
        rs0 += __shfl_xor_sync(0xffffffffu, rs0, 2);
        rs1 += __shfl_xor_sync(0xffffffffu, rs1, 1);
        rs1 += __shfl_xor_sync(0xffffffffu, rs1, 2);
        l0 = l0 * corr0 + rs0;
        l1 = l1 * corr1 + rs1;

#pragma unroll
        for (int ni = 0; ni < 8; ni++) {
            o[ni][0] *= corr0; o[ni][1] *= corr0;
            o[ni][2] *= corr1; o[ni][3] *= corr1;
        }

        // ---- P -> smem (tf32), per-warp rows ----
#pragma unroll
        for (int ni = 0; ni < 8; ni++) {
            *(uint2*)&psu[r0 * AST + ni * 8 + 2 * t] =
                make_uint2(f2tf(s[ni][0]), f2tf(s[ni][1]));
            *(uint2*)&psu[r1 * AST + ni * 8 + 2 * t] =
                make_uint2(f2tf(s[ni][2]), f2tf(s[ni][3]));
        }
        __syncwarp();

        // ---- O += P @ V ----
#pragma unroll
        for (int kk = 0; kk < 8; kk++) {
            const int k8 = kk * 8;
            uint32_t a0 = psu[r0 * AST + k8 + t];
            uint32_t a1 = psu[r1 * AST + k8 + t];
            uint32_t a2 = psu[r0 * AST + k8 + t + 4];
            uint32_t a3 = psu[r1 * AST + k8 + t + 4];
#pragma unroll
            for (int ni = 0; ni < 8; ni++) {
                uint32_t b0 = vsu[(k8 + t) * AST + ni * 8 + g];
                uint32_t b1 = vsu[(k8 + t + 4) * AST + ni * 8 + g];
                MMA_TF32(o[ni], a0, a1, a2, a3, b0, b1);
            }
        }
    }

    // ---- write y as tf32: y[b, n, h*64 + d] ----
    int b = bh / HH, h = bh % HH;
    float inv0 = 1.f / l0, inv1 = 1.f / l1;
    int n0 = qt * 128 + r0, n1 = qt * 128 + r1;
    uint32_t* y0 = g_y + ((size_t)(b * NN + n0)) * CC + h * DD;
    uint32_t* y1 = g_y + ((size_t)(b * NN + n1)) * CC + h * DD;
#pragma unroll
    for (int ni = 0; ni < 8; ni++) {
        *(uint2*)&y0[ni * 8 + 2 * t] = make_uint2(f2tf(o[ni][0] * inv0), f2tf(o[ni][1] * inv0));
        *(uint2*)&y1[ni * 8 + 2 * t] = make_uint2(f2tf(o[ni][2] * inv1), f2tf(o[ni][3] * inv1));
    }
}

// ---------------- launch ----------------
extern "C" void kernel_launch(void* const* d_in, const int* in_sizes, int n_in,
                              void* d_out, int out_size) {
    const float* x     = (const float*)d_in[0];
    const float* wqkv  = (const float*)d_in[1];
    const float* wproj = (const float*)d_in[2];
    float* out = (float*)d_out;

    void *p_xt, *p_wqkvt, *p_wprojt, *p_y;
    cudaGetSymbolAddress(&p_xt, g_xt);
    cudaGetSymbolAddress(&p_wqkvt, g_wqkvt);
    cudaGetSymbolAddress(&p_wprojt, g_wprojt);
    cudaGetSymbolAddress(&p_y, g_y);

    const int gemm_smem = 4 * TILE_F * (int)sizeof(float);           // 73728
    const int qkv_smem  = gemm_smem + 128 * 4 * (int)sizeof(float2); // +4096
    const int attn_smem = A_SMEM_U32 * (int)sizeof(uint32_t);        // 104448
    cudaFuncSetAttribute(gemm_proj, cudaFuncAttributeMaxDynamicSharedMemorySize, gemm_smem);
    cudaFuncSetAttribute(gemm_qkv_ln, cudaFuncAttributeMaxDynamicSharedMemorySize, qkv_smem);
    cudaFuncSetAttribute(attn_mma, cudaFuncAttributeMaxDynamicSharedMemorySize, attn_smem);

    // 0) convert inputs to tf32 once
    conv_tf32<<<(M_ROWS * CC / 4 + 255) / 256, 256>>>((const float4*)x, (uint4*)p_xt, M_ROWS * CC / 4);
    conv_tf32<<<(QKV_COLS * CC / 4 + 255) / 256, 256>>>((const float4*)wqkv, (uint4*)p_wqkvt, QKV_COLS * CC / 4);
    conv_tf32<<<(CC * CC / 4 + 255) / 256, 256>>>((const float4*)wproj, (uint4*)p_wprojt, CC * CC / 4);

    // 1) QKV GEMM + fused LN/split -> g_q/g_k/g_v (tf32)
    {
        dim3 grid(QKV_COLS / 128, M_ROWS / 128);
        gemm_qkv_ln<<<grid, 256, qkv_smem>>>();
    }
    // 2) Attention (tensor core) -> g_y (tf32)
    {
        dim3 grid(NN / 128, BB * HH);
        attn_mma<<<grid, 256, attn_smem>>>();
    }
    // 3) Output projection -> d_out (fp32)
    {
        dim3 grid(CC / 128, M_ROWS / 128);
        gemm_proj<<<grid, 256, gemm_smem>>>((const uint32_t*)p_y, (const uint32_t*)p_wprojt,
                                            out, M_ROWS, CC, CC);
    }
}

// round 5
// speedup vs baseline: 5.6488x; 1.1491x over previous
#include <cuda_runtime.h>
#include <math.h>
#include <stdint.h>

#define BB 8
#define NN 1024
#define CC 768
#define HH 12
#define DD 64
#define M_ROWS (BB*NN)          // 8192
#define QKV_COLS (3*CC)         // 2304
#define SCALE_Q 0.125f
#define LOG2E 1.4426950408889634f
#define LN_EPS 1e-5f

// ---------------- scratch (tf32 payloads stored as uint32) ----------------
__device__ uint32_t g_xt[(size_t)M_ROWS * CC];
__device__ uint32_t g_wqkvt[(size_t)QKV_COLS * CC];
__device__ uint32_t g_wprojt[(size_t)CC * CC];
__device__ uint32_t g_q[(size_t)BB*HH*NN*DD];   // LN'd * (SCALE_Q*LOG2E), tf32
__device__ uint32_t g_k[(size_t)BB*HH*NN*DD];   // LN'd, tf32
__device__ uint32_t g_v[(size_t)BB*HH*NN*DD];   // tf32
__device__ uint32_t g_y[(size_t)M_ROWS * CC];   // attn out, tf32

// ---------------- helpers ----------------
__device__ __forceinline__ uint32_t f2tf(float x) {
    uint32_t u;
    asm("cvt.rna.tf32.f32 %0, %1;" : "=r"(u) : "f"(x));
    return u;
}
__device__ __forceinline__ void cp16(uint32_t s, const void* g) {
    asm volatile("cp.async.cg.shared.global [%0], [%1], 16;" :: "r"(s), "l"(g));
}
#define MMA_TF32(C, A0, A1, A2, A3, B0, B1)                                   \
    asm volatile(                                                             \
        "mma.sync.aligned.m16n8k8.row.col.f32.tf32.tf32.f32 "                 \
        "{%0,%1,%2,%3},{%4,%5,%6,%7},{%8,%9},{%0,%1,%2,%3};"                  \
        : "+f"(C[0]), "+f"(C[1]), "+f"(C[2]), "+f"(C[3])                      \
        : "r"(A0), "r"(A1), "r"(A2), "r"(A3), "r"(B0), "r"(B1))

// ---------------- fp32 -> tf32 bulk convert ----------------
__global__ __launch_bounds__(256) void conv_tf32(const float4* __restrict__ in,
                                                 uint4* __restrict__ out, int n4) {
    int i = blockIdx.x * 256 + threadIdx.x;
    if (i < n4) {
        float4 v = in[i];
        out[i] = make_uint4(f2tf(v.x), f2tf(v.y), f2tf(v.z), f2tf(v.w));
    }
}

// ---------------- GEMM core (unchanged from R4) ----------------
#define GBK  32
#define GSTR 36
#define TILE_F (128*GSTR)

__device__ __forceinline__ void gemm_mainloop(const uint32_t* __restrict__ A,
                                              const uint32_t* __restrict__ W,
                                              uint32_t* As, uint32_t* Bs,
                                              int bm, int bn, int Kdim,
                                              int tid, int wm, int wn, int g, int t,
                                              float c[4][4][4]) {
    uint32_t sA0 = (uint32_t)__cvta_generic_to_shared(As);
    uint32_t sB0 = (uint32_t)__cvta_generic_to_shared(Bs);
    const int KT = Kdim / GBK;
    {
#pragma unroll
        for (int l = 0; l < 4; l++) {
            int i = tid + l * 256;
            int m = i >> 3, kc = (i & 7) * 4;
            cp16(sA0 + (uint32_t)(m * GSTR + kc) * 4, A + (size_t)(bm + m) * Kdim + kc);
            cp16(sB0 + (uint32_t)(m * GSTR + kc) * 4, W + (size_t)(bn + m) * Kdim + kc);
        }
        asm volatile("cp.async.commit_group;");
    }
    for (int kt = 0; kt < KT; kt++) {
        int buf = kt & 1;
        if (kt + 1 < KT) {
            int k0 = (kt + 1) * GBK;
            uint32_t dA = sA0 + (uint32_t)((buf ^ 1) * TILE_F) * 4;
            uint32_t dB = sB0 + (uint32_t)((buf ^ 1) * TILE_F) * 4;
#pragma unroll
            for (int l = 0; l < 4; l++) {
                int i = tid + l * 256;
                int m = i >> 3, kc = (i & 7) * 4;
                cp16(dA + (uint32_t)(m * GSTR + kc) * 4, A + (size_t)(bm + m) * Kdim + k0 + kc);
                cp16(dB + (uint32_t)(m * GSTR + kc) * 4, W + (size_t)(bn + m) * Kdim + k0 + kc);
            }
            asm volatile("cp.async.commit_group;");
            asm volatile("cp.async.wait_group 1;");
        } else {
            asm volatile("cp.async.wait_group 0;");
        }
        __syncthreads();

        const uint32_t* Ab = As + buf * TILE_F;
        const uint32_t* Bb = Bs + buf * TILE_F;
#pragma unroll
        for (int kk = 0; kk < 4; kk++) {
            const int k8 = kk * 8;
            uint32_t af[4][4], bf[4][2];
#pragma unroll
            for (int mi = 0; mi < 4; mi++) {
                const uint32_t* p = Ab + (wm + mi * 16 + g) * GSTR + k8 + t;
                const uint32_t* p8 = p + 8 * GSTR;
                af[mi][0] = p[0];
                af[mi][1] = p8[0];
                af[mi][2] = p[4];
                af[mi][3] = p8[4];
            }
#pragma unroll
            for (int ni = 0; ni < 4; ni++) {
                const uint32_t* p = Bb + (wn + ni * 8 + g) * GSTR + k8 + t;
                bf[ni][0] = p[0];
                bf[ni][1] = p[4];
            }
#pragma unroll
            for (int mi = 0; mi < 4; mi++)
#pragma unroll
                for (int ni = 0; ni < 4; ni++)
                    MMA_TF32(c[mi][ni], af[mi][0], af[mi][1], af[mi][2], af[mi][3],
                             bf[ni][0], bf[ni][1]);
        }
        __syncthreads();
    }
}

// ---------------- proj GEMM: fp32 output ----------------
__global__ __launch_bounds__(256, 2) void gemm_proj(const uint32_t* __restrict__ A,
                                                    const uint32_t* __restrict__ W,
                                                    float* __restrict__ Cmat,
                                                    int Mdim, int Ndim, int Kdim) {
    extern __shared__ uint32_t smu[];
    uint32_t* As = smu;
    uint32_t* Bs = smu + 2 * TILE_F;
    const int tid = threadIdx.x;
    const int bm = blockIdx.y * 128;
    const int bn = blockIdx.x * 128;
    const int lane = tid & 31;
    const int w = tid >> 5;
    const int wm = (w & 1) * 64;
    const int wn = (w >> 1) * 32;
    const int g = lane >> 2;
    const int t = lane & 3;

    float c[4][4][4];
#pragma unroll
    for (int mi = 0; mi < 4; mi++)
#pragma unroll
        for (int ni = 0; ni < 4; ni++)
#pragma unroll
            for (int r = 0; r < 4; r++) c[mi][ni][r] = 0.f;

    gemm_mainloop(A, W, As, Bs, bm, bn, Kdim, tid, wm, wn, g, t, c);

#pragma unroll
    for (int mi = 0; mi < 4; mi++) {
#pragma unroll
        for (int ni = 0; ni < 4; ni++) {
            int gm = bm + wm + mi * 16 + g;
            int gn = bn + wn + ni * 8 + 2 * t;
            *(float2*)&Cmat[(size_t)gm * Ndim + gn] = make_float2(c[mi][ni][0], c[mi][ni][1]);
            *(float2*)&Cmat[(size_t)(gm + 8) * Ndim + gn] = make_float2(c[mi][ni][2], c[mi][ni][3]);
        }
    }
}

// ---------------- QKV GEMM with fused LayerNorm+split epilogue (unchanged) ----------------
__global__ __launch_bounds__(256, 2) void gemm_qkv_ln() {
    extern __shared__ uint32_t smu[];
    uint32_t* As = smu;
    uint32_t* Bs = smu + 2 * TILE_F;
    float2* psm = (float2*)(smu + 4 * TILE_F);

    const int tid = threadIdx.x;
    const int bm = blockIdx.y * 128;
    const int bn = blockIdx.x * 128;
    const int lane = tid & 31;
    const int w = tid >> 5;
    const int wm = (w & 1) * 64;
    const int wn = (w >> 1) * 32;
    const int g = lane >> 2;
    const int t = lane & 3;

    float c[4][4][4];
#pragma unroll
    for (int mi = 0; mi < 4; mi++)
#pragma unroll
        for (int ni = 0; ni < 4; ni++)
#pragma unroll
            for (int r = 0; r < 4; r++) c[mi][ni][r] = 0.f;

    gemm_mainloop(g_xt, g_wqkvt, As, Bs, bm, bn, CC, tid, wm, wn, g, t, c);

    const int s = bn / CC;
    const int colb = bn % CC;
    const int h = (colb + wn) >> 6;
    const int dbase = wn & 63;
    uint32_t* dst_arr = (s == 0) ? g_q : (s == 1 ? g_k : g_v);

    if (s == 2) {
#pragma unroll
        for (int mi = 0; mi < 4; mi++) {
#pragma unroll
            for (int r = 0; r < 2; r++) {
                int m = bm + wm + mi * 16 + g + 8 * r;
                int b = m >> 10, n = m & 1023;
                uint32_t* dst = dst_arr + (((size_t)(b * HH + h)) * NN + n) * DD + dbase;
#pragma unroll
                for (int ni = 0; ni < 4; ni++)
                    *(uint2*)&dst[ni * 8 + 2 * t] =
                        make_uint2(f2tf(c[mi][ni][2 * r]), f2tf(c[mi][ni][2 * r + 1]));
            }
        }
        return;
    }

    const int hl = wn >> 6;
    const int half = (wn >> 5) & 1;
#pragma unroll
    for (int mi = 0; mi < 4; mi++) {
#pragma unroll
        for (int r = 0; r < 2; r++) {
            float sum = 0.f, sq = 0.f;
#pragma unroll
            for (int ni = 0; ni < 4; ni++) {
                float v0 = c[mi][ni][2 * r], v1 = c[mi][ni][2 * r + 1];
                sum += v0 + v1;
                sq += v0 * v0 + v1 * v1;
            }
            sum += __shfl_xor_sync(0xffffffffu, sum, 1);
            sq  += __shfl_xor_sync(0xffffffffu, sq, 1);
            sum += __shfl_xor_sync(0xffffffffu, sum, 2);
            sq  += __shfl_xor_sync(0xffffffffu, sq, 2);
            if (t == 0) {
                int row = wm + mi * 16 + g + 8 * r;
                psm[row * 4 + hl * 2 + half] = make_float2(sum, sq);
            }
        }
    }
    __syncthreads();

    const float fscale = (s == 0) ? (SCALE_Q * LOG2E) : 1.0f;
#pragma unroll
    for (int mi = 0; mi < 4; mi++) {
#pragma unroll
        for (int r = 0; r < 2; r++) {
            int row = wm + mi * 16 + g + 8 * r;
            float2 pa = psm[row * 4 + hl * 2 + 0];
            float2 pb = psm[row * 4 + hl * 2 + 1];
            float mean = (pa.x + pb.x) * (1.f / 64.f);
            float var = (pa.y + pb.y) * (1.f / 64.f) - mean * mean;
            float sc = rsqrtf(var + LN_EPS) * fscale;
            int m = bm + row;
            int b = m >> 10, n = m & 1023;
            uint32_t* dst = dst_arr + (((size_t)(b * HH + h)) * NN + n) * DD + dbase;
#pragma unroll
            for (int ni = 0; ni < 4; ni++)
                *(uint2*)&dst[ni * 8 + 2 * t] =
                    make_uint2(f2tf((c[mi][ni][2 * r] - mean) * sc),
                               f2tf((c[mi][ni][2 * r + 1] - mean) * sc));
        }
    }
}

// ---------------- tensor-core flash attention (double-buffered, shfl P relayout) ---------
// smem (u32): Q[128*68] | K[2][64*68] | V[2][64*72]
#define ASTK 68
#define ASTV 72
#define AQ_SZ   (128*ASTK)      // 8704
#define AK_SZ   (64*ASTK)       // 4352
#define AV_SZ   (64*ASTV)       // 4608
#define AK_OFF  AQ_SZ           // 8704
#define AV_OFF  (AQ_SZ + 2*AK_SZ)  // 17408
#define A_SMEM_U32 (AQ_SZ + 2*AK_SZ + 2*AV_SZ)   // 26624 u32 = 106496 B

__global__ __launch_bounds__(256, 2) void attn_mma() {
    extern __shared__ uint32_t smu[];
    uint32_t* qsu = smu;
    uint32_t* ks_ = smu + AK_OFF;
    uint32_t* vs_ = smu + AV_OFF;

    const int tid = threadIdx.x;
    const int lane = tid & 31;
    const int w = tid >> 5;
    const int g = lane >> 2;
    const int t = lane & 3;
    const int mrow = w * 16;
    const int bh = blockIdx.y;
    const int qt = blockIdx.x;
    const size_t base = (size_t)bh * NN * DD;

    uint32_t sq0 = (uint32_t)__cvta_generic_to_shared(qsu);
    uint32_t sk0 = (uint32_t)__cvta_generic_to_shared(ks_);
    uint32_t sv0 = (uint32_t)__cvta_generic_to_shared(vs_);

    // stage Q + K0 + V0
    {
        const uint32_t* qg = g_q + base + (size_t)qt * 128 * DD;
#pragma unroll
        for (int l = 0; l < 8; l++) {
            int i = tid + l * 256;
            int row = i >> 4, c4 = (i & 15) << 2;
            cp16(sq0 + (uint32_t)(row * ASTK + c4) * 4, qg + row * DD + c4);
        }
        const uint32_t* kg = g_k + base;
        const uint32_t* vg = g_v + base;
#pragma unroll
        for (int l = 0; l < 4; l++) {
            int i = tid + l * 256;
            int row = i >> 4, c4 = (i & 15) << 2;
            cp16(sk0 + (uint32_t)(row * ASTK + c4) * 4, kg + row * DD + c4);
            cp16(sv0 + (uint32_t)(row * ASTV + c4) * 4, vg + row * DD + c4);
        }
        asm volatile("cp.async.commit_group;");
    }

    float m0 = -INFINITY, m1 = -INFINITY, l0 = 0.f, l1 = 0.f;
    float o[8][4];
#pragma unroll
    for (int ni = 0; ni < 8; ni++)
#pragma unroll
        for (int r = 0; r < 4; r++) o[ni][r] = 0.f;

    const int r0 = mrow + g, r1 = mrow + g + 8;
    const int srcA = (lane & ~3) | (t >> 1);   // shfl base lane for P relayout

    for (int tkv = 0; tkv < 16; tkv++) {
        asm volatile("cp.async.wait_group 0;");
        __syncthreads();

        // prefetch next tile into other stage
        if (tkv + 1 < 16) {
            int st = (tkv + 1) & 1;
            const uint32_t* kg = g_k + base + (size_t)(tkv + 1) * 64 * DD;
            const uint32_t* vg = g_v + base + (size_t)(tkv + 1) * 64 * DD;
            uint32_t dk = sk0 + (uint32_t)(st * AK_SZ) * 4;
            uint32_t dv = sv0 + (uint32_t)(st * AV_SZ) * 4;
#pragma unroll
            for (int l = 0; l < 4; l++) {
                int i = tid + l * 256;
                int row = i >> 4, c4 = (i & 15) << 2;
                cp16(dk + (uint32_t)(row * ASTK + c4) * 4, kg + row * DD + c4);
                cp16(dv + (uint32_t)(row * ASTV + c4) * 4, vg + row * DD + c4);
            }
            asm volatile("cp.async.commit_group;");
        }

        const uint32_t* K = ks_ + (tkv & 1) * AK_SZ;
        const uint32_t* V = vs_ + (tkv & 1) * AV_SZ;

        // ---- S = Q @ K^T ----
        float s[8][4];
#pragma unroll
        for (int ni = 0; ni < 8; ni++)
#pragma unroll
            for (int r = 0; r < 4; r++) s[ni][r] = 0.f;

#pragma unroll
        for (int kk = 0; kk < 8; kk++) {
            const int k8 = kk * 8;
            uint32_t a0 = qsu[r0 * ASTK + k8 + t];
            uint32_t a1 = qsu[r1 * ASTK + k8 + t];
            uint32_t a2 = qsu[r0 * ASTK + k8 + t + 4];
            uint32_t a3 = qsu[r1 * ASTK + k8 + t + 4];
#pragma unroll
            for (int ni = 0; ni < 8; ni++) {
                uint32_t b0 = K[(ni * 8 + g) * ASTK + k8 + t];
                uint32_t b1 = K[(ni * 8 + g) * ASTK + k8 + t + 4];
                MMA_TF32(s[ni], a0, a1, a2, a3, b0, b1);
            }
        }

        // ---- online softmax (log2 domain) ----
        float mx0 = s[0][0], mx1 = s[0][2];
#pragma unroll
        for (int ni = 0; ni < 8; ni++) {
            mx0 = fmaxf(mx0, fmaxf(s[ni][0], s[ni][1]));
            mx1 = fmaxf(mx1, fmaxf(s[ni][2], s[ni][3]));
        }
        mx0 = fmaxf(mx0, __shfl_xor_sync(0xffffffffu, mx0, 1));
        mx0 = fmaxf(mx0, __shfl_xor_sync(0xffffffffu, mx0, 2));
        mx1 = fmaxf(mx1, __shfl_xor_sync(0xffffffffu, mx1, 1));
        mx1 = fmaxf(mx1, __shfl_xor_sync(0xffffffffu, mx1, 2));
        float mn0 = fmaxf(m0, mx0), mn1 = fmaxf(m1, mx1);
        float corr0 = exp2f(m0 - mn0), corr1 = exp2f(m1 - mn1);
        m0 = mn0; m1 = mn1;

        float rs0 = 0.f, rs1 = 0.f;
        uint32_t pu[8][4];
#pragma unroll
        for (int ni = 0; ni < 8; ni++) {
            float p0 = exp2f(s[ni][0] - mn0);
            float p1 = exp2f(s[ni][1] - mn0);
            float p2 = exp2f(s[ni][2] - mn1);
            float p3 = exp2f(s[ni][3] - mn1);
            rs0 += p0 + p1;
            rs1 += p2 + p3;
            pu[ni][0] = f2tf(p0);
            pu[ni][1] = f2tf(p1);
            pu[ni][2] = f2tf(p2);
            pu[ni][3] = f2tf(p3);
        }
        rs0 += __shfl_xor_sync(0xffffffffu, rs0, 1);
        rs0 += __shfl_xor_sync(0xffffffffu, rs0, 2);
        rs1 += __shfl_xor_sync(0xffffffffu, rs1, 1);
        rs1 += __shfl_xor_sync(0xffffffffu, rs1, 2);
        l0 = l0 * corr0 + rs0;
        l1 = l1 * corr1 + rs1;

#pragma unroll
        for (int ni = 0; ni < 8; ni++) {
            o[ni][0] *= corr0; o[ni][1] *= corr0;
            o[ni][2] *= corr1; o[ni][3] *= corr1;
        }

        // ---- O += P @ V : relayout P via shfl, B-frags from V ----
#pragma unroll
        for (int kk = 0; kk < 8; kk++) {
            const int k8 = kk * 8;
            uint32_t e00 = __shfl_sync(0xffffffffu, pu[kk][0], srcA);
            uint32_t e01 = __shfl_sync(0xffffffffu, pu[kk][1], srcA);
            uint32_t e10 = __shfl_sync(0xffffffffu, pu[kk][0], srcA + 2);
            uint32_t e11 = __shfl_sync(0xffffffffu, pu[kk][1], srcA + 2);
            uint32_t f00 = __shfl_sync(0xffffffffu, pu[kk][2], srcA);
            uint32_t f01 = __shfl_sync(0xffffffffu, pu[kk][3], srcA);
            uint32_t f10 = __shfl_sync(0xffffffffu, pu[kk][2], srcA + 2);
            uint32_t f11 = __shfl_sync(0xffffffffu, pu[kk][3], srcA + 2);
            uint32_t a0 = (t & 1) ? e01 : e00;
            uint32_t a2 = (t & 1) ? e11 : e10;
            uint32_t a1 = (t & 1) ? f01 : f00;
            uint32_t a3 = (t & 1) ? f11 : f10;
#pragma unroll
            for (int ni = 0; ni < 8; ni++) {
                uint32_t b0 = V[(k8 + t) * ASTV + ni * 8 + g];
                uint32_t b1 = V[(k8 + t + 4) * ASTV + ni * 8 + g];
                MMA_TF32(o[ni], a0, a1, a2, a3, b0, b1);
            }
        }
    }

    // ---- write y as tf32 ----
    int b = bh / HH, h = bh % HH;
    float inv0 = 1.f / l0, inv1 = 1.f / l1;
    int n0 = qt * 128 + r0, n1 = qt * 128 + r1;
    uint32_t* y0 = g_y + ((size_t)(b * NN + n0)) * CC + h * DD;
    uint32_t* y1 = g_y + ((size_t)(b * NN + n1)) * CC + h * DD;
#pragma unroll
    for (int ni = 0; ni < 8; ni++) {
        *(uint2*)&y0[ni * 8 + 2 * t] = make_uint2(f2tf(o[ni][0] * inv0), f2tf(o[ni][1] * inv0));
        *(uint2*)&y1[ni * 8 + 2 * t] = make_uint2(f2tf(o[ni][2] * inv1), f2tf(o[ni][3] * inv1));
    }
}

// ---------------- launch ----------------
extern "C" void kernel_launch(void* const* d_in, const int* in_sizes, int n_in,
                              void* d_out, int out_size) {
    const float* x     = (const float*)d_in[0];
    const float* wqkv  = (const float*)d_in[1];
    const float* wproj = (const float*)d_in[2];
    float* out = (float*)d_out;

    void *p_xt, *p_wqkvt, *p_wprojt, *p_y;
    cudaGetSymbolAddress(&p_xt, g_xt);
    cudaGetSymbolAddress(&p_wqkvt, g_wqkvt);
    cudaGetSymbolAddress(&p_wprojt, g_wprojt);
    cudaGetSymbolAddress(&p_y, g_y);

    const int gemm_smem = 4 * TILE_F * (int)sizeof(float);
    const int qkv_smem  = gemm_smem + 128 * 4 * (int)sizeof(float2);
    const int attn_smem = A_SMEM_U32 * (int)sizeof(uint32_t);   // 106496
    cudaFuncSetAttribute(gemm_proj, cudaFuncAttributeMaxDynamicSharedMemorySize, gemm_smem);
    cudaFuncSetAttribute(gemm_qkv_ln, cudaFuncAttributeMaxDynamicSharedMemorySize, qkv_smem);
    cudaFuncSetAttribute(attn_mma, cudaFuncAttributeMaxDynamicSharedMemorySize, attn_smem);

    conv_tf32<<<(M_ROWS * CC / 4 + 255) / 256, 256>>>((const float4*)x, (uint4*)p_xt, M_ROWS * CC / 4);
    conv_tf32<<<(QKV_COLS * CC / 4 + 255) / 256, 256>>>((const float4*)wqkv, (uint4*)p_wqkvt, QKV_COLS * CC / 4);
    conv_tf32<<<(CC * CC / 4 + 255) / 256, 256>>>((const float4*)wproj, (uint4*)p_wprojt, CC * CC / 4);

    {
        dim3 grid(QKV_COLS / 128, M_ROWS / 128);
        gemm_qkv_ln<<<grid, 256, qkv_smem>>>();
    }
    {
        dim3 grid(NN / 128, BB * HH);
        attn_mma<<<grid, 256, attn_smem>>>();
    }
    {
        dim3 grid(CC / 128, M_ROWS / 128);
        gemm_proj<<<grid, 256, gemm_smem>>>((const uint32_t*)p_y, (const uint32_t*)p_wprojt,
                                            out, M_ROWS, CC, CC);
    }
}

// round 6
// speedup vs baseline: 5.8731x; 1.0397x over previous
#include <cuda_runtime.h>
#include <math.h>
#include <stdint.h>

#define BB 8
#define NN 1024
#define CC 768
#define HH 12
#define DD 64
#define M_ROWS (BB*NN)          // 8192
#define QKV_COLS (3*CC)         // 2304
#define SCALE_Q 0.125f
#define LOG2E 1.4426950408889634f
#define LN_EPS 1e-5f

// All K-contracted operands are stored "k-interleaved": within each group of 8
// k-values, order is [0,4,1,5,2,6,3,7], so an mma fragment pair (k=t, k=t+4)
// is contiguous (positions 2t, 2t+1) -> one LDS.64.

// ---------------- scratch ----------------
__device__ uint32_t g_xt[(size_t)M_ROWS * CC];        // x, tf32, k-interleaved
__device__ uint32_t g_wqkvt[(size_t)QKV_COLS * CC];   // k-interleaved
__device__ uint32_t g_wprojt[(size_t)CC * CC];        // k-interleaved
__device__ uint32_t g_q[(size_t)BB*HH*NN*DD];         // LN'd*(SCALE*LOG2E), d-interleaved
__device__ uint32_t g_k[(size_t)BB*HH*NN*DD];         // LN'd, d-interleaved
__device__ uint32_t g_v[(size_t)BB*HH*NN*DD];         // plain
__device__ uint32_t g_y[(size_t)M_ROWS * CC];         // attn out, k-interleaved

// ---------------- helpers ----------------
__device__ __forceinline__ uint32_t f2tf(float x) {
    uint32_t u;
    asm("cvt.rna.tf32.f32 %0, %1;" : "=r"(u) : "f"(x));
    return u;
}
__device__ __forceinline__ void cp16(uint32_t s, const void* g) {
    asm volatile("cp.async.cg.shared.global [%0], [%1], 16;" :: "r"(s), "l"(g));
}
#define MMA_TF32(C, A0, A1, A2, A3, B0, B1)                                   \
    asm volatile(                                                             \
        "mma.sync.aligned.m16n8k8.row.col.f32.tf32.tf32.f32 "                 \
        "{%0,%1,%2,%3},{%4,%5,%6,%7},{%8,%9},{%0,%1,%2,%3};"                  \
        : "+f"(C[0]), "+f"(C[1]), "+f"(C[2]), "+f"(C[3])                      \
        : "r"(A0), "r"(A1), "r"(A2), "r"(A3), "r"(B0), "r"(B1))

// ---------------- fp32 -> tf32 convert + k-interleave (8 elems / thread) ----------------
__global__ __launch_bounds__(256) void conv_tf32i(const float4* __restrict__ in,
                                                  uint4* __restrict__ out, int n8) {
    int i = blockIdx.x * 256 + threadIdx.x;
    if (i < n8) {
        float4 a = in[2 * i];
        float4 b = in[2 * i + 1];
        out[2 * i]     = make_uint4(f2tf(a.x), f2tf(b.x), f2tf(a.y), f2tf(b.y));
        out[2 * i + 1] = make_uint4(f2tf(a.z), f2tf(b.z), f2tf(a.w), f2tf(b.w));
    }
}

// ---------------- GEMM core ----------------
#define GBK  32
#define GSTR 40
#define TILE_F (128*GSTR)       // 5120 u32 per stage per operand

__device__ __forceinline__ void gemm_mainloop(const uint32_t* __restrict__ A,
                                              const uint32_t* __restrict__ W,
                                              uint32_t* As, uint32_t* Bs,
                                              int bm, int bn, int Kdim,
                                              int tid, int wm, int wn, int g, int t,
                                              float c[4][4][4]) {
    uint32_t sA0 = (uint32_t)__cvta_generic_to_shared(As);
    uint32_t sB0 = (uint32_t)__cvta_generic_to_shared(Bs);
    const int KT = Kdim / GBK;
    // prologue: stage 0
    {
#pragma unroll
        for (int l = 0; l < 4; l++) {
            int i = tid + l * 256;
            int m = i >> 3, kc = (i & 7) * 4;
            cp16(sA0 + (uint32_t)(m * GSTR + kc) * 4, A + (size_t)(bm + m) * Kdim + kc);
            cp16(sB0 + (uint32_t)(m * GSTR + kc) * 4, W + (size_t)(bn + m) * Kdim + kc);
        }
        asm volatile("cp.async.commit_group;");
    }
    for (int kt = 0; kt < KT; kt++) {
        int buf = kt & 1;
        asm volatile("cp.async.wait_group 0;");
        __syncthreads();
        if (kt + 1 < KT) {
            int k0 = (kt + 1) * GBK;
            uint32_t dA = sA0 + (uint32_t)((buf ^ 1) * TILE_F) * 4;
            uint32_t dB = sB0 + (uint32_t)((buf ^ 1) * TILE_F) * 4;
#pragma unroll
            for (int l = 0; l < 4; l++) {
                int i = tid + l * 256;
                int m = i >> 3, kc = (i & 7) * 4;
                cp16(dA + (uint32_t)(m * GSTR + kc) * 4, A + (size_t)(bm + m) * Kdim + k0 + kc);
                cp16(dB + (uint32_t)(m * GSTR + kc) * 4, W + (size_t)(bn + m) * Kdim + k0 + kc);
            }
            asm volatile("cp.async.commit_group;");
        }

        const uint32_t* Ab = As + buf * TILE_F;
        const uint32_t* Bb = Bs + buf * TILE_F;
#pragma unroll
        for (int kk = 0; kk < 4; kk++) {
            const int k8 = kk * 8;
            uint32_t af[4][4], bf[4][2];
#pragma unroll
            for (int mi = 0; mi < 4; mi++) {
                const uint32_t* p = Ab + (wm + mi * 16 + g) * GSTR + k8 + 2 * t;
                uint2 lo = *(const uint2*)p;               // (k=t, k=t+4) row g
                uint2 hi = *(const uint2*)(p + 8 * GSTR);  // row g+8
                af[mi][0] = lo.x; af[mi][1] = hi.x;
                af[mi][2] = lo.y; af[mi][3] = hi.y;
            }
#pragma unroll
            for (int ni = 0; ni < 4; ni++) {
                uint2 bb = *(const uint2*)(Bb + (wn + ni * 8 + g) * GSTR + k8 + 2 * t);
                bf[ni][0] = bb.x; bf[ni][1] = bb.y;
            }
#pragma unroll
            for (int mi = 0; mi < 4; mi++)
#pragma unroll
                for (int ni = 0; ni < 4; ni++)
                    MMA_TF32(c[mi][ni], af[mi][0], af[mi][1], af[mi][2], af[mi][3],
                             bf[ni][0], bf[ni][1]);
        }
    }
}

// ---------------- proj GEMM: fp32 output (plain layout) ----------------
__global__ __launch_bounds__(256, 2) void gemm_proj(const uint32_t* __restrict__ A,
                                                    const uint32_t* __restrict__ W,
                                                    float* __restrict__ Cmat,
                                                    int Mdim, int Ndim, int Kdim) {
    extern __shared__ uint32_t smu[];
    uint32_t* As = smu;
    uint32_t* Bs = smu + 2 * TILE_F;
    const int tid = threadIdx.x;
    const int bm = blockIdx.y * 128;
    const int bn = blockIdx.x * 128;
    const int lane = tid & 31;
    const int w = tid >> 5;
    const int wm = (w & 1) * 64;
    const int wn = (w >> 1) * 32;
    const int g = lane >> 2;
    const int t = lane & 3;

    float c[4][4][4];
#pragma unroll
    for (int mi = 0; mi < 4; mi++)
#pragma unroll
        for (int ni = 0; ni < 4; ni++)
#pragma unroll
            for (int r = 0; r < 4; r++) c[mi][ni][r] = 0.f;

    gemm_mainloop(A, W, As, Bs, bm, bn, Kdim, tid, wm, wn, g, t, c);

#pragma unroll
    for (int mi = 0; mi < 4; mi++) {
#pragma unroll
        for (int ni = 0; ni < 4; ni++) {
            int gm = bm + wm + mi * 16 + g;
            int gn = bn + wn + ni * 8 + 2 * t;
            *(float2*)&Cmat[(size_t)gm * Ndim + gn] = make_float2(c[mi][ni][0], c[mi][ni][1]);
            *(float2*)&Cmat[(size_t)(gm + 8) * Ndim + gn] = make_float2(c[mi][ni][2], c[mi][ni][3]);
        }
    }
}

// ---------------- QKV GEMM with fused LayerNorm+split epilogue ----------------
__global__ __launch_bounds__(256, 2) void gemm_qkv_ln() {
    extern __shared__ uint32_t smu[];
    uint32_t* As = smu;
    uint32_t* Bs = smu + 2 * TILE_F;
    float2* psm = (float2*)(smu + 4 * TILE_F);

    const int tid = threadIdx.x;
    const int bm = blockIdx.y * 128;
    const int bn = blockIdx.x * 128;
    const int lane = tid & 31;
    const int w = tid >> 5;
    const int wm = (w & 1) * 64;
    const int wn = (w >> 1) * 32;
    const int g = lane >> 2;
    const int t = lane & 3;

    float c[4][4][4];
#pragma unroll
    for (int mi = 0; mi < 4; mi++)
#pragma unroll
        for (int ni = 0; ni < 4; ni++)
#pragma unroll
            for (int r = 0; r < 4; r++) c[mi][ni][r] = 0.f;

    gemm_mainloop(g_xt, g_wqkvt, As, Bs, bm, bn, CC, tid, wm, wn, g, t, c);
    __syncthreads();   // mainloop's last iteration has no trailing sync; protect psm reuse

    const int s = bn / CC;
    const int colb = bn % CC;
    const int h = (colb + wn) >> 6;
    const int dbase = wn & 63;
    uint32_t* dst_arr = (s == 0) ? g_q : (s == 1 ? g_k : g_v);
    const int p0 = (t < 2) ? 4 * t : 4 * t - 7;     // interleaved position of col 2t

    if (s == 2) {
        // v: plain layout
#pragma unroll
        for (int mi = 0; mi < 4; mi++) {
#pragma unroll
            for (int r = 0; r < 2; r++) {
                int m = bm + wm + mi * 16 + g + 8 * r;
                int b = m >> 10, n = m & 1023;
                uint32_t* dst = dst_arr + (((size_t)(b * HH + h)) * NN + n) * DD + dbase;
#pragma unroll
                for (int ni = 0; ni < 4; ni++)
                    *(uint2*)&dst[ni * 8 + 2 * t] =
                        make_uint2(f2tf(c[mi][ni][2 * r]), f2tf(c[mi][ni][2 * r + 1]));
            }
        }
        return;
    }

    const int hl = wn >> 6;
    const int half = (wn >> 5) & 1;
#pragma unroll
    for (int mi = 0; mi < 4; mi++) {
#pragma unroll
        for (int r = 0; r < 2; r++) {
            float sum = 0.f, sq = 0.f;
#pragma unroll
            for (int ni = 0; ni < 4; ni++) {
                float v0 = c[mi][ni][2 * r], v1 = c[mi][ni][2 * r + 1];
                sum += v0 + v1;
                sq += v0 * v0 + v1 * v1;
            }
            sum += __shfl_xor_sync(0xffffffffu, sum, 1);
            sq  += __shfl_xor_sync(0xffffffffu, sq, 1);
            sum += __shfl_xor_sync(0xffffffffu, sum, 2);
            sq  += __shfl_xor_sync(0xffffffffu, sq, 2);
            if (t == 0) {
                int row = wm + mi * 16 + g + 8 * r;
                psm[row * 4 + hl * 2 + half] = make_float2(sum, sq);
            }
        }
    }
    __syncthreads();

    const float fscale = (s == 0) ? (SCALE_Q * LOG2E) : 1.0f;
#pragma unroll
    for (int mi = 0; mi < 4; mi++) {
#pragma unroll
        for (int r = 0; r < 2; r++) {
            int row = wm + mi * 16 + g + 8 * r;
            float2 pa = psm[row * 4 + hl * 2 + 0];
            float2 pb = psm[row * 4 + hl * 2 + 1];
            float mean = (pa.x + pb.x) * (1.f / 64.f);
            float var = (pa.y + pb.y) * (1.f / 64.f) - mean * mean;
            float sc = rsqrtf(var + LN_EPS) * fscale;
            int m = bm + row;
            int b = m >> 10, n = m & 1023;
            uint32_t* dst = dst_arr + (((size_t)(b * HH + h)) * NN + n) * DD + dbase;
#pragma unroll
            for (int ni = 0; ni < 4; ni++) {
                dst[ni * 8 + p0]     = f2tf((c[mi][ni][2 * r] - mean) * sc);
                dst[ni * 8 + p0 + 2] = f2tf((c[mi][ni][2 * r + 1] - mean) * sc);
            }
        }
    }
}

// ---------------- tensor-core flash attention ----------------
// smem (u32), stride 72 everywhere: Q[128*72] | K[2][64*72] | V[2][64*72]
#define AST 72
#define AQ_SZ  (128*AST)        // 9216
#define AKV_SZ (64*AST)         // 4608
#define AK_OFF AQ_SZ
#define AV_OFF (AQ_SZ + 2*AKV_SZ)
#define A_SMEM_U32 (AQ_SZ + 4*AKV_SZ)   // 27648 u32 = 110592 B

__global__ __launch_bounds__(256, 2) void attn_mma() {
    extern __shared__ uint32_t smu[];
    uint32_t* qsu = smu;
    uint32_t* ks_ = smu + AK_OFF;
    uint32_t* vs_ = smu + AV_OFF;

    const int tid = threadIdx.x;
    const int lane = tid & 31;
    const int w = tid >> 5;
    const int g = lane >> 2;
    const int t = lane & 3;
    const int mrow = w * 16;
    const int bh = blockIdx.y;
    const int qt = blockIdx.x;
    const size_t base = (size_t)bh * NN * DD;

    uint32_t sq0 = (uint32_t)__cvta_generic_to_shared(qsu);
    uint32_t sk0 = (uint32_t)__cvta_generic_to_shared(ks_);
    uint32_t sv0 = (uint32_t)__cvta_generic_to_shared(vs_);

    // stage Q + K0 + V0
    {
        const uint32_t* qg = g_q + base + (size_t)qt * 128 * DD;
#pragma unroll
        for (int l = 0; l < 8; l++) {
            int i = tid + l * 256;
            int row = i >> 4, c4 = (i & 15) << 2;
            cp16(sq0 + (uint32_t)(row * AST + c4) * 4, qg + row * DD + c4);
        }
        const uint32_t* kg = g_k + base;
        const uint32_t* vg = g_v + base;
#pragma unroll
        for (int l = 0; l < 4; l++) {
            int i = tid + l * 256;
            int row = i >> 4, c4 = (i & 15) << 2;
            cp16(sk0 + (uint32_t)(row * AST + c4) * 4, kg + row * DD + c4);
            cp16(sv0 + (uint32_t)(row * AST + c4) * 4, vg + row * DD + c4);
        }
        asm volatile("cp.async.commit_group;");
    }

    float m0 = -INFINITY, m1 = -INFINITY, l0 = 0.f, l1 = 0.f;
    float o[8][4];
#pragma unroll
    for (int ni = 0; ni < 8; ni++)
#pragma unroll
        for (int r = 0; r < 4; r++) o[ni][r] = 0.f;

    const int r0 = mrow + g, r1 = mrow + g + 8;
    const int srcA = (lane & ~3) | (t >> 1);

    for (int tkv = 0; tkv < 16; tkv++) {
        asm volatile("cp.async.wait_group 0;");
        __syncthreads();

        if (tkv + 1 < 16) {
            int st = (tkv + 1) & 1;
            const uint32_t* kg = g_k + base + (size_t)(tkv + 1) * 64 * DD;
            const uint32_t* vg = g_v + base + (size_t)(tkv + 1) * 64 * DD;
            uint32_t dk = sk0 + (uint32_t)(st * AKV_SZ) * 4;
            uint32_t dv = sv0 + (uint32_t)(st * AKV_SZ) * 4;
#pragma unroll
            for (int l = 0; l < 4; l++) {
                int i = tid + l * 256;
                int row = i >> 4, c4 = (i & 15) << 2;
                cp16(dk + (uint32_t)(row * AST + c4) * 4, kg + row * DD + c4);
                cp16(dv + (uint32_t)(row * AST + c4) * 4, vg + row * DD + c4);
            }
            asm volatile("cp.async.commit_group;");
        }

        const uint32_t* K = ks_ + (tkv & 1) * AKV_SZ;
        const uint32_t* V = vs_ + (tkv & 1) * AKV_SZ;

        // ---- S = Q @ K^T (interleaved d -> LDS.64 frags) ----
        float s[8][4];
#pragma unroll
        for (int ni = 0; ni < 8; ni++)
#pragma unroll
            for (int r = 0; r < 4; r++) s[ni][r] = 0.f;

#pragma unroll
        for (int kk = 0; kk < 8; kk++) {
            const int k8 = kk * 8;
            uint2 qa = *(const uint2*)&qsu[r0 * AST + k8 + 2 * t];   // a0, a2
            uint2 qb = *(const uint2*)&qsu[r1 * AST + k8 + 2 * t];   // a1, a3
#pragma unroll
            for (int ni = 0; ni < 8; ni++) {
                uint2 kb = *(const uint2*)&K[(ni * 8 + g) * AST + k8 + 2 * t];
                MMA_TF32(s[ni], qa.x, qb.x, qa.y, qb.y, kb.x, kb.y);
            }
        }

        // ---- online softmax (log2 domain) ----
        float mx0 = s[0][0], mx1 = s[0][2];
#pragma unroll
        for (int ni = 0; ni < 8; ni++) {
            mx0 = fmaxf(mx0, fmaxf(s[ni][0], s[ni][1]));
            mx1 = fmaxf(mx1, fmaxf(s[ni][2], s[ni][3]));
        }
        mx0 = fmaxf(mx0, __shfl_xor_sync(0xffffffffu, mx0, 1));
        mx0 = fmaxf(mx0, __shfl_xor_sync(0xffffffffu, mx0, 2));
        mx1 = fmaxf(mx1, __shfl_xor_sync(0xffffffffu, mx1, 1));
        mx1 = fmaxf(mx1, __shfl_xor_sync(0xffffffffu, mx1, 2));
        float mn0 = fmaxf(m0, mx0), mn1 = fmaxf(m1, mx1);
        float corr0 = exp2f(m0 - mn0), corr1 = exp2f(m1 - mn1);
        m0 = mn0; m1 = mn1;

        float rs0 = 0.f, rs1 = 0.f;
        uint32_t pu[8][4];
#pragma unroll
        for (int ni = 0; ni < 8; ni++) {
            float p0 = exp2f(s[ni][0] - mn0);
            float p1 = exp2f(s[ni][1] - mn0);
            float p2 = exp2f(s[ni][2] - mn1);
            float p3 = exp2f(s[ni][3] - mn1);
            rs0 += p0 + p1;
            rs1 += p2 + p3;
            pu[ni][0] = f2tf(p0);
            pu[ni][1] = f2tf(p1);
            pu[ni][2] = f2tf(p2);
            pu[ni][3] = f2tf(p3);
        }
        rs0 += __shfl_xor_sync(0xffffffffu, rs0, 1);
        rs0 += __shfl_xor_sync(0xffffffffu, rs0, 2);
        rs1 += __shfl_xor_sync(0xffffffffu, rs1, 1);
        rs1 += __shfl_xor_sync(0xffffffffu, rs1, 2);
        l0 = l0 * corr0 + rs0;
        l1 = l1 * corr1 + rs1;

#pragma unroll
        for (int ni = 0; ni < 8; ni++) {
            o[ni][0] *= corr0; o[ni][1] *= corr0;
            o[ni][2] *= corr1; o[ni][3] *= corr1;
        }

        // ---- O += P @ V : P relayout via shfl; V plain layout ----
#pragma unroll
        for (int kk = 0; kk < 8; kk++) {
            const int k8 = kk * 8;
            uint32_t e00 = __shfl_sync(0xffffffffu, pu[kk][0], srcA);
            uint32_t e01 = __shfl_sync(0xffffffffu, pu[kk][1], srcA);
            uint32_t e10 = __shfl_sync(0xffffffffu, pu[kk][0], srcA + 2);
            uint32_t e11 = __shfl_sync(0xffffffffu, pu[kk][1], srcA + 2);
            uint32_t f00 = __shfl_sync(0xffffffffu, pu[kk][2], srcA);
            uint32_t f01 = __shfl_sync(0xffffffffu, pu[kk][3], srcA);
            uint32_t f10 = __shfl_sync(0xffffffffu, pu[kk][2], srcA + 2);
            uint32_t f11 = __shfl_sync(0xffffffffu, pu[kk][3], srcA + 2);
            uint32_t a0 = (t & 1) ? e01 : e00;
            uint32_t a2 = (t & 1) ? e11 : e10;
            uint32_t a1 = (t & 1) ? f01 : f00;
            uint32_t a3 = (t & 1) ? f11 : f10;
#pragma unroll
            for (int ni = 0; ni < 8; ni++) {
                uint32_t b0 = V[(k8 + t) * AST + ni * 8 + g];
                uint32_t b1 = V[(k8 + t + 4) * AST + ni * 8 + g];
                MMA_TF32(o[ni], a0, a1, a2, a3, b0, b1);
            }
        }
    }

    // ---- write y (k-interleaved for proj) ----
    int b = bh / HH, h = bh % HH;
    float inv0 = 1.f / l0, inv1 = 1.f / l1;
    int n0 = qt * 128 + r0, n1 = qt * 128 + r1;
    uint32_t* y0 = g_y + ((size_t)(b * NN + n0)) * CC + h * DD;
    uint32_t* y1 = g_y + ((size_t)(b * NN + n1)) * CC + h * DD;
    const int p0i = (t < 2) ? 4 * t : 4 * t - 7;
#pragma unroll
    for (int ni = 0; ni < 8; ni++) {
        y0[ni * 8 + p0i]     = f2tf(o[ni][0] * inv0);
        y0[ni * 8 + p0i + 2] = f2tf(o[ni][1] * inv0);
        y1[ni * 8 + p0i]     = f2tf(o[ni][2] * inv1);
        y1[ni * 8 + p0i + 2] = f2tf(o[ni][3] * inv1);
    }
}

// ---------------- launch ----------------
extern "C" void kernel_launch(void* const* d_in, const int* in_sizes, int n_in,
                              void* d_out, int out_size) {
    const float* x     = (const float*)d_in[0];
    const float* wqkv  = (const float*)d_in[1];
    const float* wproj = (const float*)d_in[2];
    float* out = (float*)d_out;

    void *p_xt, *p_wqkvt, *p_wprojt, *p_y;
    cudaGetSymbolAddress(&p_xt, g_xt);
    cudaGetSymbolAddress(&p_wqkvt, g_wqkvt);
    cudaGetSymbolAddress(&p_wprojt, g_wprojt);
    cudaGetSymbolAddress(&p_y, g_y);

    const int gemm_smem = 4 * TILE_F * (int)sizeof(uint32_t);          // 81920
    const int qkv_smem  = gemm_smem + 128 * 4 * (int)sizeof(float2);   // +4096
    const int attn_smem = A_SMEM_U32 * (int)sizeof(uint32_t);          // 110592
    cudaFuncSetAttribute(gemm_proj, cudaFuncAttributeMaxDynamicSharedMemorySize, gemm_smem);
    cudaFuncSetAttribute(gemm_qkv_ln, cudaFuncAttributeMaxDynamicSharedMemorySize, qkv_smem);
    cudaFuncSetAttribute(attn_mma, cudaFuncAttributeMaxDynamicSharedMemorySize, attn_smem);

    conv_tf32i<<<(M_ROWS * CC / 8 + 255) / 256, 256>>>((const float4*)x, (uint4*)p_xt, M_ROWS * CC / 8);
    conv_tf32i<<<(QKV_COLS * CC / 8 + 255) / 256, 256>>>((const float4*)wqkv, (uint4*)p_wqkvt, QKV_COLS * CC / 8);
    conv_tf32i<<<(CC * CC / 8 + 255) / 256, 256>>>((const float4*)wproj, (uint4*)p_wprojt, CC * CC / 8);

    {
        dim3 grid(QKV_COLS / 128, M_ROWS / 128);
        gemm_qkv_ln<<<grid, 256, qkv_smem>>>();
    }
    {
        dim3 grid(NN / 128, BB * HH);
        attn_mma<<<grid, 256, attn_smem>>>();
    }
    {
        dim3 grid(CC / 128, M_ROWS / 128);
        gemm_proj<<<grid, 256, gemm_smem>>>((const uint32_t*)p_y, (const uint32_t*)p_wprojt,
                                            out, M_ROWS, CC, CC);
    }
}